// round 13
// baseline (speedup 1.0000x reference)
#include <cuda_runtime.h>
#include <math.h>
#include <stdint.h>

#define DD  96
#define PLN (DD*DD)
#define VOL (DD*DD*DD)
#define NC  16
#define SSTR2 72                     // S row stride in bf16 halves (144B)
#define PLANE_H (192*SSTR2)          // halves per plane (13824)
#define PLANE_B (PLANE_H*2)          // 27648 bytes
#define SMEM_BYTES (2*PLANE_B)       // 55296

__device__ __align__(16) float g_A[NC*VOL];
__device__ __align__(16) float g_B[NC*VOL];
__device__ __align__(16) float g_alive0[VOL];
__device__ unsigned g_maxPre[5];
__device__ unsigned g_maxPost[4];

typedef unsigned long long u64t;
__device__ __align__(16) u64t  g_Wq[8*9*12];        // conv weight pairs, padded
__device__ u64t  g_Bpp[24];                          // conv bias pairs
__device__ __align__(16) uint4 g_Wb1[3*8*32];        // bf16 hi/lo B-frags (K perm applied)
__device__ __align__(16) uint4 g_Wb2[4*8*32];
__device__ __align__(16) uint4 g_Wb3[4*2*32];

__device__ __forceinline__ unsigned encf(float f) {
    unsigned u = __float_as_uint(f);
    return (u & 0x80000000u) ? ~u : (u | 0x80000000u);
}
__device__ __forceinline__ float decf(unsigned e) {
    return __uint_as_float((e & 0x80000000u) ? (e ^ 0x80000000u) : ~e);
}
__device__ __forceinline__ float tanh_fast(float x) {
    float y; asm("tanh.approx.f32 %0, %1;" : "=f"(y) : "f"(x)); return y;
}
__device__ __forceinline__ u64t pack2(float lo, float hi) {
    u64t r; asm("mov.b64 %0, {%1, %2};" : "=l"(r) : "f"(lo), "f"(hi)); return r;
}
__device__ __forceinline__ void unpack2(u64t v, float& lo, float& hi) {
    asm("mov.b64 {%0, %1}, %2;" : "=f"(lo), "=f"(hi) : "l"(v));
}
__device__ __forceinline__ u64t ffma2(u64t a, u64t b, u64t c) {
    u64t d; asm("fma.rn.f32x2 %0, %1, %2, %3;" : "=l"(d) : "l"(a), "l"(b), "l"(c)); return d;
}
__device__ __forceinline__ uint32_t bf16x2_rn(float f0, float f1) {
    uint32_t r;  // {low=bf16(f0), high=bf16(f1)}
    asm("cvt.rn.bf16x2.f32 %0, %1, %2;" : "=r"(r) : "f"(f1), "f"(f0));
    return r;
}
// store fp32 pair (cols col, col+1) as hi/lo bf16 planes, XOR-swizzled 16B chunks
__device__ __forceinline__ void st_pair(uint16_t* Shi, uint16_t* Slo, int row, int col,
                                        float f0, float f1) {
    uint32_t u0 = __float_as_uint(f0), u1 = __float_as_uint(f1);
    uint32_t hp = __byte_perm(u0, u1, 0x7632);           // {hi16(f0), hi16(f1)}
    float r0 = f0 - __uint_as_float(u0 & 0xFFFF0000u);   // exact residual
    float r1 = f1 - __uint_as_float(u1 & 0xFFFF0000u);
    uint32_t lp = bf16x2_rn(r0, r1);
    int chunk = (col >> 3) ^ ((row >> 3) & 7);
    int idx = row*SSTR2 + (chunk << 3) + (col & 7);
    *(uint32_t*)&Shi[idx] = hp;
    *(uint32_t*)&Slo[idx] = lp;
}
__device__ __forceinline__ void mma_bf16(float* c, const uint32_t* a, uint32_t b0, uint32_t b1) {
    asm volatile("mma.sync.aligned.m16n8k16.row.col.f32.bf16.bf16.f32 "
        "{%0,%1,%2,%3}, {%4,%5,%6,%7}, {%8,%9}, {%0,%1,%2,%3};"
        : "+f"(c[0]), "+f"(c[1]), "+f"(c[2]), "+f"(c[3])
        : "r"(a[0]), "r"(a[1]), "r"(a[2]), "r"(a[3]), "r"(b0), "r"(b1));
}
__device__ __forceinline__ void ldm_x4(uint32_t addr, uint32_t* r) {
    asm volatile("ldmatrix.sync.aligned.m8n8.x4.shared.b16 {%0,%1,%2,%3}, [%4];"
        : "=r"(r[0]), "=r"(r[1]), "=r"(r[2]), "=r"(r[3]) : "r"(addr));
}
__device__ __forceinline__ uint32_t smem_u32(const void* p) {
    uint32_t a; asm("{ .reg .u64 t; cvta.to.shared.u64 t, %1; cvt.u32.u64 %0, t; }" : "=r"(a) : "l"(p));
    return a;
}

__device__ __forceinline__ int inv_perm(int s) {
    int c2 = s / 6, r = s % 6, j = r >> 1, b = r & 1;
    return (2*c2 + b)*3 + j;
}

__global__ void init_kernel() {
    int t = threadIdx.x;
    if (t < 5) g_maxPre[t]  = 0x007FFFFFu;
    if (t < 4) g_maxPost[t] = 0x007FFFFFu;
}

__device__ __forceinline__ uint4 make_bfrag(float w00, float w01, float w10, float w11) {
    uint32_t u00 = __float_as_uint(w00), u01 = __float_as_uint(w01);
    uint32_t u10 = __float_as_uint(w10), u11 = __float_as_uint(w11);
    uint4 f;
    f.x = __byte_perm(u00, u01, 0x7632);
    f.y = __byte_perm(u10, u11, 0x7632);
    f.z = bf16x2_rn(w00 - __uint_as_float(u00 & 0xFFFF0000u),
                    w01 - __uint_as_float(u01 & 0xFFFF0000u));
    f.w = bf16x2_rn(w10 - __uint_as_float(u10 & 0xFFFF0000u),
                    w11 - __uint_as_float(u11 & 0xFFFF0000u));
    return f;
}

__global__ void prep_weights(const float* __restrict__ w_perc, const float* __restrict__ b_perc,
                             const float* __restrict__ w1, const float* __restrict__ w2,
                             const float* __restrict__ w3) {
    int t = threadIdx.x;
    for (int idx = t; idx < 8*9*9; idx += 256) {
        int c2 = idx / 81, r = idx % 81, dh = r / 9, kk = r % 9, kw = kk / 3, j = kk % 3;
        int kf = dh*3 + kw;
        g_Wq[(c2*9 + dh)*12 + kw*3 + j] =
            pack2(w_perc[((2*c2)*3 + j)*27 + kf], w_perc[((2*c2+1)*3 + j)*27 + kf]);
    }
    if (t < 24) {
        int c2 = t / 3, j = t % 3;
        g_Bpp[t] = pack2(b_perc[(2*c2)*3 + j], b_perc[(2*c2+1)*3 + j]);
    }
    for (int idx = t; idx < 3*8*32; idx += 256) {
        int kt = idx >> 8, n = (idx >> 5) & 7, l = idx & 31;
        int g = l >> 2, q = l & 3, ro = n*8 + g;
        int s0 = kt*16 + 2*q;
        g_Wb1[idx] = make_bfrag(w1[ro*48 + inv_perm(s0)],   w1[ro*48 + inv_perm(s0+1)],
                                w1[ro*48 + inv_perm(s0+8)], w1[ro*48 + inv_perm(s0+9)]);
    }
    for (int idx = t; idx < 4*8*32; idx += 256) {
        int kt = idx >> 8, n = (idx >> 5) & 7, l = idx & 31;
        int g = l >> 2, q = l & 3, ro = n*8 + g;
        int s0 = kt*16 + 2*q;
        g_Wb2[idx] = make_bfrag(w2[ro*64 + s0],   w2[ro*64 + s0+1],
                                w2[ro*64 + s0+8], w2[ro*64 + s0+9]);
    }
    for (int idx = t; idx < 4*2*32; idx += 256) {
        int kt = idx >> 6, n = (idx >> 5) & 1, l = idx & 31;
        int g = l >> 2, q = l & 3, ro = n*8 + g;
        int s0 = kt*16 + 2*q;
        g_Wb3[idx] = make_bfrag(w3[ro*64 + s0],   w3[ro*64 + s0+1],
                                w3[ro*64 + s0+8], w3[ro*64 + s0+9]);
    }
}

__global__ void reduce_ch3_kernel(const float* __restrict__ p) {
    float m = -INFINITY;
    for (int i = blockIdx.x * blockDim.x + threadIdx.x; i < VOL; i += gridDim.x * blockDim.x)
        m = fmaxf(m, p[i]);
    #pragma unroll
    for (int s = 16; s > 0; s >>= 1) m = fmaxf(m, __shfl_xor_sync(0xffffffffu, m, s));
    __shared__ float sm[8];
    if ((threadIdx.x & 31) == 0) sm[threadIdx.x >> 5] = m;
    __syncthreads();
    if (threadIdx.x == 0) {
        int nw = (blockDim.x + 31) / 32;
        float mm = sm[0];
        for (int i = 1; i < nw; i++) mm = fmaxf(mm, sm[i]);
        atomicMax(&g_maxPre[0], encf(mm));
    }
}

// MMA pass over swizzled bf16 hi/lo planes: 32 rows x NT*8 outputs, KT k16-tiles.
template<int KT, int NT>
__device__ __forceinline__ void mma_pass(uint32_t rowHi, uint32_t rowLo,
                                         uint32_t xr, uint32_t hi4,
                                         const uint4* __restrict__ Wf,
                                         int lane, float C[2][NT][4])
{
    #pragma unroll
    for (int m = 0; m < 2; m++)
        #pragma unroll
        for (int n = 0; n < NT; n++)
            #pragma unroll
            for (int i = 0; i < 4; i++) C[m][n][i] = 0.0f;

    #pragma unroll
    for (int k = 0; k < KT; k++) {
        uint32_t off0 = ((2u*k + hi4) ^ xr) << 4;
        uint32_t off1 = ((2u*k + hi4) ^ xr ^ 2u) << 4;   // rows +16: xr flips bit1
        uint32_t h0[4], h1[4], l0[4], l1[4];
        ldm_x4(rowHi + off0, h0);
        ldm_x4(rowHi + 16*SSTR2*2 + off1, h1);
        ldm_x4(rowLo + off0, l0);
        ldm_x4(rowLo + 16*SSTR2*2 + off1, l1);
        #pragma unroll
        for (int n = 0; n < NT; n++) {
            uint4 wf = Wf[(k*NT + n)*32 + lane];
            mma_bf16(C[0][n], h0, wf.x, wf.y);
            mma_bf16(C[0][n], l0, wf.x, wf.y);
            mma_bf16(C[0][n], h0, wf.z, wf.w);
            mma_bf16(C[1][n], h1, wf.x, wf.y);
            mma_bf16(C[1][n], l1, wf.x, wf.y);
            mma_bf16(C[1][n], h1, wf.z, wf.w);
        }
    }
}

// Update: block = 192 voxels (2 h-rows), 192 threads (1 voxel each), 6 warps.
// Warp w owns MLP rows [32w, 32w+32) == the rows its own threads wrote -> warp-sync only.
__global__ __launch_bounds__(192, 3) void update_kernel(
    const float* __restrict__ xin,
    const float* __restrict__ b1, const float* __restrict__ b2, const float* __restrict__ b3,
    int step)
{
    const float* cur = (step == 0) ? xin : (const float*)g_A;

    extern __shared__ uint16_t SH[];
    uint16_t* Shi = SH;
    uint16_t* Slo = SH + PLANE_H;
    __shared__ float sb1[64], sb2[64], sb3[16];

    const int t = threadIdx.x;
    const int lane = t & 31;
    if (t < 64) { sb1[t] = b1[t]; sb2[t] = b2[t]; }
    else if (t >= 64 && t < 80) sb3[t - 64] = b3[t - 64];
    __syncthreads();

    const int bb = blockIdx.x * 192;
    const int d  = blockIdx.x / 48;
    const int h0 = (blockIdx.x % 48) * 2;
    const int w0 = t % 96;
    const int h  = h0 + t / 96;
    const int p0 = bb + t;

    const bool vD[3] = { d > 0, true, d < DD-1 };
    const bool vH[3] = { h > 0, true, h < DD-1 };
    const bool wl = (w0 > 0), wr = (w0 < 95);

    // ---- depthwise conv: 1 voxel/thread, edge taps via warp shuffle ----
    {
        float aliv = -INFINITY;
        #pragma unroll 2
        for (int c2 = 0; c2 < 8; c2++) {
            u64t f0 = g_Bpp[c2*3+0], f1 = g_Bpp[c2*3+1], f2 = g_Bpp[c2*3+2];
            const float* baseA = cur + (2*c2)*VOL;
            const float* baseB = baseA + VOL;
            #pragma unroll
            for (int kd = 0; kd < 3; kd++)
                #pragma unroll
                for (int kh = 0; kh < 3; kh++) {
                    const bool v = vD[kd] && vH[kh];
                    const int nb = p0 + (kd-1)*PLN + (kh-1)*DD;
                    float ca = 0.0f, cb = 0.0f;
                    if (v) { ca = baseA[nb]; cb = baseB[nb]; }
                    float ma = __shfl_up_sync(0xffffffffu, ca, 1);
                    float mb = __shfl_up_sync(0xffffffffu, cb, 1);
                    float pa = __shfl_down_sync(0xffffffffu, ca, 1);
                    float pb = __shfl_down_sync(0xffffffffu, cb, 1);
                    if (lane == 0 && v && wl)  { ma = baseA[nb-1]; mb = baseB[nb-1]; }
                    if (lane == 31 && v && wr) { pa = baseA[nb+1]; pb = baseB[nb+1]; }
                    if (!wl) { ma = 0.0f; mb = 0.0f; }
                    if (!wr) { pa = 0.0f; pb = 0.0f; }
                    if (c2 == 1 && v) {   // channel 3 alive pool
                        aliv = fmaxf(aliv, cb);
                        if (wl) aliv = fmaxf(aliv, mb);
                        if (wr) aliv = fmaxf(aliv, pb);
                    }
                    const ulonglong2* wp2 = reinterpret_cast<const ulonglong2*>(
                        g_Wq + (c2*9 + kd*3 + kh)*12);
                    ulonglong2 q0 = wp2[0], q1 = wp2[1], q2 = wp2[2], q3 = wp2[3];
                    u64t w8 = reinterpret_cast<const u64t*>(wp2)[8];
                    u64t Pm = pack2(ma, mb), Pc = pack2(ca, cb), Pp = pack2(pa, pb);
                    f0 = ffma2(Pm, q0.x, f0); f1 = ffma2(Pm, q0.y, f1); f2 = ffma2(Pm, q1.x, f2);
                    f0 = ffma2(Pc, q1.y, f0); f1 = ffma2(Pc, q2.x, f1); f2 = ffma2(Pc, q2.y, f2);
                    f0 = ffma2(Pp, q3.x, f0); f1 = ffma2(Pp, q3.y, f1); f2 = ffma2(Pp, w8,   f2);
                }
            float lo, hi;
            unpack2(f0, lo, hi); st_pair(Shi, Slo, t, 6*c2+0, lo, hi);
            unpack2(f1, lo, hi); st_pair(Shi, Slo, t, 6*c2+2, lo, hi);
            unpack2(f2, lo, hi); st_pair(Shi, Slo, t, 6*c2+4, lo, hi);
        }
        g_alive0[p0] = aliv;
    }
    __syncwarp();

    const int wid = t >> 5;
    const int g = lane >> 2, q = lane & 3;
    const uint32_t sbase = smem_u32(Shi);
    const uint32_t hi4 = lane >> 4;
    float m3 = -INFINITY;

    const int base_r = wid * 32;
    const int rr = base_r + (lane & 15);
    const uint32_t xr = ((uint32_t)rr >> 3) & 7u;
    const uint32_t rowHi = sbase + rr*SSTR2*2;
    const uint32_t rowLo = rowHi + PLANE_B;

    // ---- layer 1: 48 -> 64, tanh ----
    {
        float C[2][8][4];
        mma_pass<3, 8>(rowHi, rowLo, xr, hi4, g_Wb1, lane, C);
        #pragma unroll
        for (int m = 0; m < 2; m++) {
            int rA = base_r + m*16 + g;
            #pragma unroll
            for (int n = 0; n < 8; n++) {
                int c0 = 8*n + 2*q;
                st_pair(Shi, Slo, rA,   c0, tanh_fast(C[m][n][0] + sb1[c0]),
                                            tanh_fast(C[m][n][1] + sb1[c0+1]));
                st_pair(Shi, Slo, rA+8, c0, tanh_fast(C[m][n][2] + sb1[c0]),
                                            tanh_fast(C[m][n][3] + sb1[c0+1]));
            }
        }
        __syncwarp();
    }

    // ---- layer 2: 64 -> 64, tanh ----
    {
        float C[2][8][4];
        mma_pass<4, 8>(rowHi, rowLo, xr, hi4, g_Wb2, lane, C);
        #pragma unroll
        for (int m = 0; m < 2; m++) {
            int rA = base_r + m*16 + g;
            #pragma unroll
            for (int n = 0; n < 8; n++) {
                int c0 = 8*n + 2*q;
                st_pair(Shi, Slo, rA,   c0, tanh_fast(C[m][n][0] + sb2[c0]),
                                            tanh_fast(C[m][n][1] + sb2[c0+1]));
                st_pair(Shi, Slo, rA+8, c0, tanh_fast(C[m][n][2] + sb2[c0]),
                                            tanh_fast(C[m][n][3] + sb2[c0+1]));
            }
        }
        __syncwarp();
    }

    // ---- layer 3: 64 -> 16, residual + store ----
    {
        float C[2][2][4];
        mma_pass<4, 2>(rowHi, rowLo, xr, hi4, g_Wb3, lane, C);
        #pragma unroll
        for (int m = 0; m < 2; m++) {
            int rA = base_r + m*16 + g;
            int pA = bb + rA, pB = pA + 8;
            #pragma unroll
            for (int n = 0; n < 2; n++) {
                int c0 = 8*n + 2*q, c1 = c0 + 1;
                float v00 = C[m][n][0] + sb3[c0] + cur[c0*VOL + pA];
                float v01 = C[m][n][1] + sb3[c1] + cur[c1*VOL + pA];
                float v10 = C[m][n][2] + sb3[c0] + cur[c0*VOL + pB];
                float v11 = C[m][n][3] + sb3[c1] + cur[c1*VOL + pB];
                g_B[c0*VOL + pA] = v00;
                g_B[c1*VOL + pA] = v01;
                g_B[c0*VOL + pB] = v10;
                g_B[c1*VOL + pB] = v11;
                if (c1 == 3) m3 = fmaxf(m3, fmaxf(v01, v11));
            }
        }
    }
    #pragma unroll
    for (int s = 16; s > 0; s >>= 1) m3 = fmaxf(m3, __shfl_xor_sync(0xffffffffu, m3, s));
    if (lane == 0) atomicMax(&g_maxPost[step], encf(m3));
}

// Finalize: 4 voxels/thread via float4. Block 96 = 24 w-quads x 4 h-rows; grid (24, 96).
__global__ __launch_bounds__(96) void finalize_kernel(
    float* __restrict__ out, int step, const int* __restrict__ pInOut)
{
    float* dst = (step == 3) ? out : (float*)g_A;

    const int t = threadIdx.x;
    const int wq = t % 24, hr = t / 24;
    const int d = blockIdx.y;
    const int h = blockIdx.x * 4 + hr;
    const int w = wq * 4;
    const int pos = d*PLN + h*DD + w;

    const bool vD[3] = { d > 0, true, d < DD-1 };
    const bool vH[3] = { h > 0, true, h < DD-1 };
    const bool wl = (w > 0), wr = (w < 92);

    const float* B3 = g_B + 3*VOL;
    float4 m4 = make_float4(-INFINITY, -INFINITY, -INFINITY, -INFINITY);
    float eL = -INFINITY, eR = -INFINITY;
    #pragma unroll
    for (int kd = 0; kd < 3; kd++)
        #pragma unroll
        for (int kh = 0; kh < 3; kh++)
            if (vD[kd] && vH[kh]) {
                int nb = pos + (kd-1)*PLN + (kh-1)*DD;
                float4 r = *reinterpret_cast<const float4*>(B3 + nb);
                m4.x = fmaxf(m4.x, r.x); m4.y = fmaxf(m4.y, r.y);
                m4.z = fmaxf(m4.z, r.z); m4.w = fmaxf(m4.w, r.w);
                if (wl) eL = fmaxf(eL, B3[nb-1]);
                if (wr) eR = fmaxf(eR, B3[nb+4]);
            }
    float m1_0 = fmaxf(fmaxf(eL,   m4.x), m4.y);
    float m1_1 = fmaxf(fmaxf(m4.x, m4.y), m4.z);
    float m1_2 = fmaxf(fmaxf(m4.y, m4.z), m4.w);
    float m1_3 = fmaxf(fmaxf(m4.z, m4.w), eR);

    float th0 = 0.1f * decf(g_maxPre[step]);  if (isnan(th0)) th0 = -INFINITY;
    float th1 = 0.1f * decf(g_maxPost[step]); if (isnan(th1)) th1 = -INFINITY;

    float4 a0 = *reinterpret_cast<const float4*>(g_alive0 + pos);
    bool zero = (d == DD-1) && (h >= *pInOut);
    float lf0 = (!zero && a0.x > th0 && m1_0 > th1) ? 1.0f : 0.0f;
    float lf1 = (!zero && a0.y > th0 && m1_1 > th1) ? 1.0f : 0.0f;
    float lf2 = (!zero && a0.z > th0 && m1_2 > th1) ? 1.0f : 0.0f;
    float lf3 = (!zero && a0.w > th0 && m1_3 > th1) ? 1.0f : 0.0f;

    float v3 = -INFINITY;
    #pragma unroll
    for (int c = 0; c < NC; c++) {
        float4 v = *reinterpret_cast<const float4*>(g_B + c*VOL + pos);
        v.x *= lf0; v.y *= lf1; v.z *= lf2; v.w *= lf3;
        *reinterpret_cast<float4*>(dst + c*VOL + pos) = v;
        if (c == 3) v3 = fmaxf(fmaxf(v.x, v.y), fmaxf(v.z, v.w));
    }

    #pragma unroll
    for (int s = 16; s > 0; s >>= 1) v3 = fmaxf(v3, __shfl_xor_sync(0xffffffffu, v3, s));
    if ((t & 31) == 0) atomicMax(&g_maxPre[step + 1], encf(v3));
}

extern "C" void kernel_launch(void* const* d_in, const int* in_sizes, int n_in,
                              void* d_out, int out_size) {
    (void)in_sizes; (void)n_in; (void)out_size;
    const float* x      = (const float*)d_in[0];
    const float* w_perc = (const float*)d_in[1];
    const float* b_perc = (const float*)d_in[2];
    const float* w1     = (const float*)d_in[3];
    const float* b1     = (const float*)d_in[4];
    const float* w2     = (const float*)d_in[5];
    const float* b2     = (const float*)d_in[6];
    const float* w3     = (const float*)d_in[7];
    const float* b3     = (const float*)d_in[8];
    const int*   pInOut = (const int*)d_in[12];
    float* out = (float*)d_out;

    static bool attr_set = false;
    if (!attr_set) {
        cudaFuncSetAttribute(update_kernel, cudaFuncAttributeMaxDynamicSharedMemorySize, SMEM_BYTES);
        attr_set = true;
    }

    init_kernel<<<1, 32>>>();
    prep_weights<<<1, 256>>>(w_perc, b_perc, w1, w2, w3);
    reduce_ch3_kernel<<<432, 256>>>(x + 3*VOL);

    dim3 fgrd(24, DD);
    for (int s = 0; s < 4; s++) {
        update_kernel<<<VOL/192, 192, SMEM_BYTES>>>(x, b1, b2, b3, s);
        finalize_kernel<<<fgrd, 96>>>(out, s, pInOut);
    }
}

// round 14
// speedup vs baseline: 1.1488x; 1.1488x over previous
#include <cuda_runtime.h>
#include <math.h>
#include <stdint.h>

#define DD  96
#define PLN (DD*DD)
#define VOL (DD*DD*DD)
#define NC  16
#define SSTR2 64                     // S row stride in bf16 halves (128B row, SW-swizzled)
#define PLANE_H (192*SSTR2)          // halves per plane (12288)
#define PLANE_B (PLANE_H*2)          // 24576 bytes
#define SMEM_BYTES (2*PLANE_B)       // 49152

__device__ __align__(16) float g_A[NC*VOL];
__device__ __align__(16) float g_B[NC*VOL];
__device__ __align__(16) float g_alive0[VOL];
__device__ unsigned g_maxPre[5];
__device__ unsigned g_maxPost[4];

typedef unsigned long long u64t;
__device__ __align__(16) u64t  g_Wq[8*9*12];        // conv weight pairs, padded
__device__ u64t  g_Bpp[24];                          // conv bias pairs
__device__ __align__(16) uint4 g_Wb1[3*8*32];        // bf16 hi/lo B-frags (K perm applied)
__device__ __align__(16) uint4 g_Wb2[4*8*32];
__device__ __align__(16) uint4 g_Wb3[4*2*32];

__device__ __forceinline__ unsigned encf(float f) {
    unsigned u = __float_as_uint(f);
    return (u & 0x80000000u) ? ~u : (u | 0x80000000u);
}
__device__ __forceinline__ float decf(unsigned e) {
    return __uint_as_float((e & 0x80000000u) ? (e ^ 0x80000000u) : ~e);
}
__device__ __forceinline__ float tanh_fast(float x) {
    float y; asm("tanh.approx.f32 %0, %1;" : "=f"(y) : "f"(x)); return y;
}
__device__ __forceinline__ u64t pack2(float lo, float hi) {
    u64t r; asm("mov.b64 %0, {%1, %2};" : "=l"(r) : "f"(lo), "f"(hi)); return r;
}
__device__ __forceinline__ void unpack2(u64t v, float& lo, float& hi) {
    asm("mov.b64 {%0, %1}, %2;" : "=f"(lo), "=f"(hi) : "l"(v));
}
__device__ __forceinline__ u64t ffma2(u64t a, u64t b, u64t c) {
    u64t d; asm("fma.rn.f32x2 %0, %1, %2, %3;" : "=l"(d) : "l"(a), "l"(b), "l"(c)); return d;
}
__device__ __forceinline__ uint32_t bf16x2_rn(float f0, float f1) {
    uint32_t r;  // {low=bf16(f0), high=bf16(f1)}
    asm("cvt.rn.bf16x2.f32 %0, %1, %2;" : "=r"(r) : "f"(f1), "f"(f0));
    return r;
}
// store fp32 pair (cols col, col+1) as hi/lo bf16 planes; SW swizzle: chunk ^= row&7
__device__ __forceinline__ void st_pair(uint16_t* Shi, uint16_t* Slo, int row, int col,
                                        float f0, float f1) {
    uint32_t u0 = __float_as_uint(f0), u1 = __float_as_uint(f1);
    uint32_t hp = __byte_perm(u0, u1, 0x7632);           // {hi16(f0), hi16(f1)}
    float r0 = f0 - __uint_as_float(u0 & 0xFFFF0000u);   // exact residual
    float r1 = f1 - __uint_as_float(u1 & 0xFFFF0000u);
    uint32_t lp = bf16x2_rn(r0, r1);
    int chunk = (col >> 3) ^ (row & 7);
    int idx = row*SSTR2 + (chunk << 3) + (col & 7);
    *(uint32_t*)&Shi[idx] = hp;
    *(uint32_t*)&Slo[idx] = lp;
}
__device__ __forceinline__ void mma_bf16(float* c, const uint32_t* a, uint32_t b0, uint32_t b1) {
    asm volatile("mma.sync.aligned.m16n8k16.row.col.f32.bf16.bf16.f32 "
        "{%0,%1,%2,%3}, {%4,%5,%6,%7}, {%8,%9}, {%0,%1,%2,%3};"
        : "+f"(c[0]), "+f"(c[1]), "+f"(c[2]), "+f"(c[3])
        : "r"(a[0]), "r"(a[1]), "r"(a[2]), "r"(a[3]), "r"(b0), "r"(b1));
}
__device__ __forceinline__ void ldm_x4(uint32_t addr, uint32_t* r) {
    asm volatile("ldmatrix.sync.aligned.m8n8.x4.shared.b16 {%0,%1,%2,%3}, [%4];"
        : "=r"(r[0]), "=r"(r[1]), "=r"(r[2]), "=r"(r[3]) : "r"(addr));
}
__device__ __forceinline__ uint32_t smem_u32(const void* p) {
    uint32_t a; asm("{ .reg .u64 t; cvta.to.shared.u64 t, %1; cvt.u32.u64 %0, t; }" : "=r"(a) : "l"(p));
    return a;
}

__device__ __forceinline__ int inv_perm(int s) {
    int c2 = s / 6, r = s % 6, j = r >> 1, b = r & 1;
    return (2*c2 + b)*3 + j;
}

__global__ void init_kernel() {
    int t = threadIdx.x;
    if (t < 5) g_maxPre[t]  = 0x007FFFFFu;
    if (t < 4) g_maxPost[t] = 0x007FFFFFu;
}

__device__ __forceinline__ uint4 make_bfrag(float w00, float w01, float w10, float w11) {
    uint32_t u00 = __float_as_uint(w00), u01 = __float_as_uint(w01);
    uint32_t u10 = __float_as_uint(w10), u11 = __float_as_uint(w11);
    uint4 f;
    f.x = __byte_perm(u00, u01, 0x7632);
    f.y = __byte_perm(u10, u11, 0x7632);
    f.z = bf16x2_rn(w00 - __uint_as_float(u00 & 0xFFFF0000u),
                    w01 - __uint_as_float(u01 & 0xFFFF0000u));
    f.w = bf16x2_rn(w10 - __uint_as_float(u10 & 0xFFFF0000u),
                    w11 - __uint_as_float(u11 & 0xFFFF0000u));
    return f;
}

__global__ void prep_weights(const float* __restrict__ w_perc, const float* __restrict__ b_perc,
                             const float* __restrict__ w1, const float* __restrict__ w2,
                             const float* __restrict__ w3) {
    int t = threadIdx.x;
    for (int idx = t; idx < 8*9*9; idx += 256) {
        int c2 = idx / 81, r = idx % 81, dh = r / 9, kk = r % 9, kw = kk / 3, j = kk % 3;
        int kf = dh*3 + kw;
        g_Wq[(c2*9 + dh)*12 + kw*3 + j] =
            pack2(w_perc[((2*c2)*3 + j)*27 + kf], w_perc[((2*c2+1)*3 + j)*27 + kf]);
    }
    if (t < 24) {
        int c2 = t / 3, j = t % 3;
        g_Bpp[t] = pack2(b_perc[(2*c2)*3 + j], b_perc[(2*c2+1)*3 + j]);
    }
    for (int idx = t; idx < 3*8*32; idx += 256) {
        int kt = idx >> 8, n = (idx >> 5) & 7, l = idx & 31;
        int g = l >> 2, q = l & 3, ro = n*8 + g;
        int s0 = kt*16 + 2*q;
        g_Wb1[idx] = make_bfrag(w1[ro*48 + inv_perm(s0)],   w1[ro*48 + inv_perm(s0+1)],
                                w1[ro*48 + inv_perm(s0+8)], w1[ro*48 + inv_perm(s0+9)]);
    }
    for (int idx = t; idx < 4*8*32; idx += 256) {
        int kt = idx >> 8, n = (idx >> 5) & 7, l = idx & 31;
        int g = l >> 2, q = l & 3, ro = n*8 + g;
        int s0 = kt*16 + 2*q;
        g_Wb2[idx] = make_bfrag(w2[ro*64 + s0],   w2[ro*64 + s0+1],
                                w2[ro*64 + s0+8], w2[ro*64 + s0+9]);
    }
    for (int idx = t; idx < 4*2*32; idx += 256) {
        int kt = idx >> 6, n = (idx >> 5) & 1, l = idx & 31;
        int g = l >> 2, q = l & 3, ro = n*8 + g;
        int s0 = kt*16 + 2*q;
        g_Wb3[idx] = make_bfrag(w3[ro*64 + s0],   w3[ro*64 + s0+1],
                                w3[ro*64 + s0+8], w3[ro*64 + s0+9]);
    }
}

__global__ void reduce_ch3_kernel(const float* __restrict__ p) {
    float m = -INFINITY;
    for (int i = blockIdx.x * blockDim.x + threadIdx.x; i < VOL; i += gridDim.x * blockDim.x)
        m = fmaxf(m, p[i]);
    #pragma unroll
    for (int s = 16; s > 0; s >>= 1) m = fmaxf(m, __shfl_xor_sync(0xffffffffu, m, s));
    __shared__ float sm[8];
    if ((threadIdx.x & 31) == 0) sm[threadIdx.x >> 5] = m;
    __syncthreads();
    if (threadIdx.x == 0) {
        int nw = (blockDim.x + 31) / 32;
        float mm = sm[0];
        for (int i = 1; i < nw; i++) mm = fmaxf(mm, sm[i]);
        atomicMax(&g_maxPre[0], encf(mm));
    }
}

// MMA pass over swizzled bf16 hi/lo planes: 32 rows x NT*8 outputs, KT k16-tiles.
// xr = (row & 7) of this lane's A-row; rows+16 share the same xr (16 % 8 == 0).
template<int KT, int NT>
__device__ __forceinline__ void mma_pass(uint32_t rowHi, uint32_t rowLo,
                                         uint32_t xr, uint32_t hi4,
                                         const uint4* __restrict__ Wf,
                                         int lane, float C[2][NT][4])
{
    #pragma unroll
    for (int m = 0; m < 2; m++)
        #pragma unroll
        for (int n = 0; n < NT; n++)
            #pragma unroll
            for (int i = 0; i < 4; i++) C[m][n][i] = 0.0f;

    #pragma unroll
    for (int k = 0; k < KT; k++) {
        uint32_t off = ((2u*k + hi4) ^ xr) << 4;
        uint32_t h0[4], h1[4], l0[4], l1[4];
        ldm_x4(rowHi + off, h0);
        ldm_x4(rowHi + 16*SSTR2*2 + off, h1);
        ldm_x4(rowLo + off, l0);
        ldm_x4(rowLo + 16*SSTR2*2 + off, l1);
        #pragma unroll
        for (int n = 0; n < NT; n++) {
            uint4 wf = Wf[(k*NT + n)*32 + lane];
            mma_bf16(C[0][n], h0, wf.x, wf.y);
            mma_bf16(C[0][n], l0, wf.x, wf.y);
            mma_bf16(C[0][n], h0, wf.z, wf.w);
            mma_bf16(C[1][n], h1, wf.x, wf.y);
            mma_bf16(C[1][n], l1, wf.x, wf.y);
            mma_bf16(C[1][n], h1, wf.z, wf.w);
        }
    }
}

// Update: block = 192 voxels (2 h-rows), 96 threads (2 voxels each), 3 warps.
__global__ __launch_bounds__(96, 4) void update_kernel(
    const float* __restrict__ xin,
    const float* __restrict__ b1, const float* __restrict__ b2, const float* __restrict__ b3,
    int step)
{
    const float* cur = (step == 0) ? xin : (const float*)g_A;

    extern __shared__ uint16_t SH[];
    uint16_t* Shi = SH;
    uint16_t* Slo = SH + PLANE_H;
    __shared__ float sb1[64], sb2[64], sb3[16];

    const int t = threadIdx.x;
    const int lane = t & 31;
    if (t < 64) { sb1[t] = b1[t]; sb2[t] = b2[t]; }
    if (t < 16) sb3[t] = b3[t];
    __syncthreads();

    const int bb = blockIdx.x * 192;
    const int d  = blockIdx.x / 48;
    const int h0 = (blockIdx.x % 48) * 2;
    const int lv = 2*t;
    const int w0 = lv % 96;
    const int h  = h0 + lv / 96;
    const int p0 = bb + lv;

    const bool vD[3] = { d > 0, true, d < DD-1 };
    const bool vH[3] = { h > 0, true, h < DD-1 };
    const bool wl = (w0 > 0), wr = (w0 < 94);

    // ---- depthwise conv: 2 voxels/thread, edge taps via warp shuffle ----
    {
        float aA = -INFINITY, aB = -INFINITY;
        #pragma unroll 2
        for (int c2 = 0; c2 < 8; c2++) {
            u64t fA0 = g_Bpp[c2*3+0], fA1 = g_Bpp[c2*3+1], fA2 = g_Bpp[c2*3+2];
            u64t fB0 = fA0, fB1 = fA1, fB2 = fA2;
            const float* baseA = cur + (2*c2)*VOL;
            const float* baseB = baseA + VOL;
            #pragma unroll
            for (int kd = 0; kd < 3; kd++)
                #pragma unroll
                for (int kh = 0; kh < 3; kh++) {
                    const bool v = vD[kd] && vH[kh];
                    const int nb = p0 + (kd-1)*PLN + (kh-1)*DD;
                    float2 ca = make_float2(0.0f, 0.0f), cb = make_float2(0.0f, 0.0f);
                    if (v) {
                        ca = *reinterpret_cast<const float2*>(baseA + nb);
                        cb = *reinterpret_cast<const float2*>(baseB + nb);
                    }
                    float ma = __shfl_up_sync(0xffffffffu, ca.y, 1);
                    float mb = __shfl_up_sync(0xffffffffu, cb.y, 1);
                    float pa = __shfl_down_sync(0xffffffffu, ca.x, 1);
                    float pb = __shfl_down_sync(0xffffffffu, cb.x, 1);
                    if (lane == 0 && v && wl)  { ma = baseA[nb-1]; mb = baseB[nb-1]; }
                    if (lane == 31 && v && wr) { pa = baseA[nb+2]; pb = baseB[nb+2]; }
                    if (!wl) { ma = 0.0f; mb = 0.0f; }
                    if (!wr) { pa = 0.0f; pb = 0.0f; }
                    if (c2 == 1 && v) {   // channel 3 (hi lane) alive pool
                        float mx = fmaxf(cb.x, cb.y);
                        aA = fmaxf(aA, mx); if (wl) aA = fmaxf(aA, mb);
                        aB = fmaxf(aB, mx); if (wr) aB = fmaxf(aB, pb);
                    }
                    const ulonglong2* wp2 = reinterpret_cast<const ulonglong2*>(
                        g_Wq + (c2*9 + kd*3 + kh)*12);
                    ulonglong2 q0 = wp2[0], q1 = wp2[1], q2 = wp2[2], q3 = wp2[3];
                    u64t w8 = reinterpret_cast<const u64t*>(wp2)[8];
                    u64t Pm = pack2(ma, mb), Pc0 = pack2(ca.x, cb.x);
                    u64t Pc1 = pack2(ca.y, cb.y), Pp = pack2(pa, pb);
                    fA0 = ffma2(Pm,  q0.x, fA0); fA1 = ffma2(Pm,  q0.y, fA1); fA2 = ffma2(Pm,  q1.x, fA2);
                    fA0 = ffma2(Pc0, q1.y, fA0); fA1 = ffma2(Pc0, q2.x, fA1); fA2 = ffma2(Pc0, q2.y, fA2);
                    fA0 = ffma2(Pc1, q3.x, fA0); fA1 = ffma2(Pc1, q3.y, fA1); fA2 = ffma2(Pc1, w8,   fA2);
                    fB0 = ffma2(Pc0, q0.x, fB0); fB1 = ffma2(Pc0, q0.y, fB1); fB2 = ffma2(Pc0, q1.x, fB2);
                    fB0 = ffma2(Pc1, q1.y, fB0); fB1 = ffma2(Pc1, q2.x, fB1); fB2 = ffma2(Pc1, q2.y, fB2);
                    fB0 = ffma2(Pp,  q3.x, fB0); fB1 = ffma2(Pp,  q3.y, fB1); fB2 = ffma2(Pp,  w8,   fB2);
                }
            float lo, hi;
            unpack2(fA0, lo, hi); st_pair(Shi, Slo, lv,   6*c2+0, lo, hi);
            unpack2(fA1, lo, hi); st_pair(Shi, Slo, lv,   6*c2+2, lo, hi);
            unpack2(fA2, lo, hi); st_pair(Shi, Slo, lv,   6*c2+4, lo, hi);
            unpack2(fB0, lo, hi); st_pair(Shi, Slo, lv+1, 6*c2+0, lo, hi);
            unpack2(fB1, lo, hi); st_pair(Shi, Slo, lv+1, 6*c2+2, lo, hi);
            unpack2(fB2, lo, hi); st_pair(Shi, Slo, lv+1, 6*c2+4, lo, hi);
        }
        *reinterpret_cast<float2*>(&g_alive0[p0]) = make_float2(aA, aB);
    }
    __syncwarp();

    const int wid = t >> 5;
    const int g = lane >> 2, q = lane & 3;
    const uint32_t sbase = smem_u32(Shi);
    const uint32_t hi4 = lane >> 4;
    float m3 = -INFINITY;

    #pragma unroll
    for (int pass = 0; pass < 2; pass++) {
        const int base_r = wid*64 + pass*32;
        const int rr = base_r + (lane & 15);
        const uint32_t xr = (uint32_t)rr & 7u;
        const uint32_t rowHi = sbase + rr*SSTR2*2;
        const uint32_t rowLo = rowHi + PLANE_B;

        // ---- layer 1: 48 -> 64, tanh ----
        {
            float C[2][8][4];
            mma_pass<3, 8>(rowHi, rowLo, xr, hi4, g_Wb1, lane, C);
            #pragma unroll
            for (int m = 0; m < 2; m++) {
                int rA = base_r + m*16 + g;
                #pragma unroll
                for (int n = 0; n < 8; n++) {
                    int c0 = 8*n + 2*q;
                    st_pair(Shi, Slo, rA,   c0, tanh_fast(C[m][n][0] + sb1[c0]),
                                                tanh_fast(C[m][n][1] + sb1[c0+1]));
                    st_pair(Shi, Slo, rA+8, c0, tanh_fast(C[m][n][2] + sb1[c0]),
                                                tanh_fast(C[m][n][3] + sb1[c0+1]));
                }
            }
            __syncwarp();
        }

        // ---- layer 2: 64 -> 64, tanh ----
        {
            float C[2][8][4];
            mma_pass<4, 8>(rowHi, rowLo, xr, hi4, g_Wb2, lane, C);
            #pragma unroll
            for (int m = 0; m < 2; m++) {
                int rA = base_r + m*16 + g;
                #pragma unroll
                for (int n = 0; n < 8; n++) {
                    int c0 = 8*n + 2*q;
                    st_pair(Shi, Slo, rA,   c0, tanh_fast(C[m][n][0] + sb2[c0]),
                                                tanh_fast(C[m][n][1] + sb2[c0+1]));
                    st_pair(Shi, Slo, rA+8, c0, tanh_fast(C[m][n][2] + sb2[c0]),
                                                tanh_fast(C[m][n][3] + sb2[c0+1]));
                }
            }
            __syncwarp();
        }

        // ---- layer 3: 64 -> 16, residual + store ----
        {
            float C[2][2][4];
            mma_pass<4, 2>(rowHi, rowLo, xr, hi4, g_Wb3, lane, C);
            #pragma unroll
            for (int m = 0; m < 2; m++) {
                int rA = base_r + m*16 + g;
                int pA = bb + rA, pB = pA + 8;
                #pragma unroll
                for (int n = 0; n < 2; n++) {
                    int c0 = 8*n + 2*q, c1 = c0 + 1;
                    float v00 = C[m][n][0] + sb3[c0] + cur[c0*VOL + pA];
                    float v01 = C[m][n][1] + sb3[c1] + cur[c1*VOL + pA];
                    float v10 = C[m][n][2] + sb3[c0] + cur[c0*VOL + pB];
                    float v11 = C[m][n][3] + sb3[c1] + cur[c1*VOL + pB];
                    g_B[c0*VOL + pA] = v00;
                    g_B[c1*VOL + pA] = v01;
                    g_B[c0*VOL + pB] = v10;
                    g_B[c1*VOL + pB] = v11;
                    if (c1 == 3) m3 = fmaxf(m3, fmaxf(v01, v11));
                }
            }
        }
        __syncwarp();
    }
    #pragma unroll
    for (int s = 16; s > 0; s >>= 1) m3 = fmaxf(m3, __shfl_xor_sync(0xffffffffu, m3, s));
    if (lane == 0) atomicMax(&g_maxPost[step], encf(m3));
}

// Finalize: 4 voxels/thread via float4. Block 96 = 24 w-quads x 4 h-rows; grid (24, 96).
__global__ __launch_bounds__(96) void finalize_kernel(
    float* __restrict__ out, int step, const int* __restrict__ pInOut)
{
    float* dst = (step == 3) ? out : (float*)g_A;

    const int t = threadIdx.x;
    const int wq = t % 24, hr = t / 24;
    const int d = blockIdx.y;
    const int h = blockIdx.x * 4 + hr;
    const int w = wq * 4;
    const int pos = d*PLN + h*DD + w;

    const bool vD[3] = { d > 0, true, d < DD-1 };
    const bool vH[3] = { h > 0, true, h < DD-1 };
    const bool wl = (w > 0), wr = (w < 92);

    const float* B3 = g_B + 3*VOL;
    float4 m4 = make_float4(-INFINITY, -INFINITY, -INFINITY, -INFINITY);
    float eL = -INFINITY, eR = -INFINITY;
    #pragma unroll
    for (int kd = 0; kd < 3; kd++)
        #pragma unroll
        for (int kh = 0; kh < 3; kh++)
            if (vD[kd] && vH[kh]) {
                int nb = pos + (kd-1)*PLN + (kh-1)*DD;
                float4 r = *reinterpret_cast<const float4*>(B3 + nb);
                m4.x = fmaxf(m4.x, r.x); m4.y = fmaxf(m4.y, r.y);
                m4.z = fmaxf(m4.z, r.z); m4.w = fmaxf(m4.w, r.w);
                if (wl) eL = fmaxf(eL, B3[nb-1]);
                if (wr) eR = fmaxf(eR, B3[nb+4]);
            }
    float m1_0 = fmaxf(fmaxf(eL,   m4.x), m4.y);
    float m1_1 = fmaxf(fmaxf(m4.x, m4.y), m4.z);
    float m1_2 = fmaxf(fmaxf(m4.y, m4.z), m4.w);
    float m1_3 = fmaxf(fmaxf(m4.z, m4.w), eR);

    float th0 = 0.1f * decf(g_maxPre[step]);  if (isnan(th0)) th0 = -INFINITY;
    float th1 = 0.1f * decf(g_maxPost[step]); if (isnan(th1)) th1 = -INFINITY;

    float4 a0 = *reinterpret_cast<const float4*>(g_alive0 + pos);
    bool zero = (d == DD-1) && (h >= *pInOut);
    float lf0 = (!zero && a0.x > th0 && m1_0 > th1) ? 1.0f : 0.0f;
    float lf1 = (!zero && a0.y > th0 && m1_1 > th1) ? 1.0f : 0.0f;
    float lf2 = (!zero && a0.z > th0 && m1_2 > th1) ? 1.0f : 0.0f;
    float lf3 = (!zero && a0.w > th0 && m1_3 > th1) ? 1.0f : 0.0f;

    float v3 = -INFINITY;
    #pragma unroll
    for (int c = 0; c < NC; c++) {
        float4 v = *reinterpret_cast<const float4*>(g_B + c*VOL + pos);
        v.x *= lf0; v.y *= lf1; v.z *= lf2; v.w *= lf3;
        *reinterpret_cast<float4*>(dst + c*VOL + pos) = v;
        if (c == 3) v3 = fmaxf(fmaxf(v.x, v.y), fmaxf(v.z, v.w));
    }

    #pragma unroll
    for (int s = 16; s > 0; s >>= 1) v3 = fmaxf(v3, __shfl_xor_sync(0xffffffffu, v3, s));
    if ((t & 31) == 0) atomicMax(&g_maxPre[step + 1], encf(v3));
}

extern "C" void kernel_launch(void* const* d_in, const int* in_sizes, int n_in,
                              void* d_out, int out_size) {
    (void)in_sizes; (void)n_in; (void)out_size;
    const float* x      = (const float*)d_in[0];
    const float* w_perc = (const float*)d_in[1];
    const float* b_perc = (const float*)d_in[2];
    const float* w1     = (const float*)d_in[3];
    const float* b1     = (const float*)d_in[4];
    const float* w2     = (const float*)d_in[5];
    const float* b2     = (const float*)d_in[6];
    const float* w3     = (const float*)d_in[7];
    const float* b3     = (const float*)d_in[8];
    const int*   pInOut = (const int*)d_in[12];
    float* out = (float*)d_out;

    static bool attr_set = false;
    if (!attr_set) {
        cudaFuncSetAttribute(update_kernel, cudaFuncAttributeMaxDynamicSharedMemorySize, SMEM_BYTES);
        attr_set = true;
    }

    init_kernel<<<1, 32>>>();
    prep_weights<<<1, 256>>>(w_perc, b_perc, w1, w2, w3);
    reduce_ch3_kernel<<<432, 256>>>(x + 3*VOL);

    dim3 fgrd(24, DD);
    for (int s = 0; s < 4; s++) {
        update_kernel<<<VOL/192, 96, SMEM_BYTES>>>(x, b1, b2, b3, s);
        finalize_kernel<<<fgrd, 96>>>(out, s, pInOut);
    }
}

// round 15
// speedup vs baseline: 1.2725x; 1.1077x over previous
#include <cuda_runtime.h>
#include <math.h>
#include <stdint.h>

#define DD  96
#define PLN (DD*DD)
#define VOL (DD*DD*DD)
#define NC  16
#define SSTR2 72                     // S row stride in bf16 halves (144B)
#define PLANE_H (192*SSTR2)          // halves per plane (13824)
#define PLANE_B (PLANE_H*2)          // 27648 bytes
#define SMEM_BYTES (2*PLANE_B)       // 55296

__device__ __align__(16) float g_A[NC*VOL];
__device__ __align__(16) float g_B[NC*VOL];
__device__ __align__(16) float g_alive0[VOL];
__device__ unsigned g_maxPre[5];
__device__ unsigned g_maxPost[4];

typedef unsigned long long u64t;
__device__ __align__(16) u64t  g_Wq[8*9*12];        // conv weight pairs, padded
__device__ u64t  g_Bpp[24];                          // conv bias pairs
__device__ __align__(16) uint4 g_Wb1[3*8*32];        // bf16 hi/lo B-frags (K perm applied)
__device__ __align__(16) uint4 g_Wb2[4*8*32];
__device__ __align__(16) uint4 g_Wb3[4*2*32];

__device__ __forceinline__ unsigned encf(float f) {
    unsigned u = __float_as_uint(f);
    return (u & 0x80000000u) ? ~u : (u | 0x80000000u);
}
__device__ __forceinline__ float decf(unsigned e) {
    return __uint_as_float((e & 0x80000000u) ? (e ^ 0x80000000u) : ~e);
}
__device__ __forceinline__ float tanh_fast(float x) {
    float y; asm("tanh.approx.f32 %0, %1;" : "=f"(y) : "f"(x)); return y;
}
__device__ __forceinline__ u64t pack2(float lo, float hi) {
    u64t r; asm("mov.b64 %0, {%1, %2};" : "=l"(r) : "f"(lo), "f"(hi)); return r;
}
__device__ __forceinline__ void unpack2(u64t v, float& lo, float& hi) {
    asm("mov.b64 {%0, %1}, %2;" : "=f"(lo), "=f"(hi) : "l"(v));
}
__device__ __forceinline__ u64t ffma2(u64t a, u64t b, u64t c) {
    u64t d; asm("fma.rn.f32x2 %0, %1, %2, %3;" : "=l"(d) : "l"(a), "l"(b), "l"(c)); return d;
}
__device__ __forceinline__ uint32_t bf16x2_rn(float f0, float f1) {
    uint32_t r;  // {low=bf16(f0), high=bf16(f1)}
    asm("cvt.rn.bf16x2.f32 %0, %1, %2;" : "=r"(r) : "f"(f1), "f"(f0));
    return r;
}
// store fp32 pair (cols col, col+1) as hi/lo bf16 planes, XOR-swizzled 16B chunks
__device__ __forceinline__ void st_pair(uint16_t* Shi, uint16_t* Slo, int row, int col,
                                        float f0, float f1) {
    uint32_t u0 = __float_as_uint(f0), u1 = __float_as_uint(f1);
    uint32_t hp = __byte_perm(u0, u1, 0x7632);           // {hi16(f0), hi16(f1)}
    float r0 = f0 - __uint_as_float(u0 & 0xFFFF0000u);   // exact residual
    float r1 = f1 - __uint_as_float(u1 & 0xFFFF0000u);
    uint32_t lp = bf16x2_rn(r0, r1);
    int chunk = (col >> 3) ^ ((row >> 3) & 7);
    int idx = row*SSTR2 + (chunk << 3) + (col & 7);
    *(uint32_t*)&Shi[idx] = hp;
    *(uint32_t*)&Slo[idx] = lp;
}
// tanh(c + b) pair -> bf16 hi/lo frag registers (same rounding as st_pair path)
__device__ __forceinline__ void cvt_frag(float c0, float c1, float b0v, float b1v,
                                         uint32_t& hi, uint32_t& lo) {
    float v0 = tanh_fast(c0 + b0v), v1 = tanh_fast(c1 + b1v);
    uint32_t u0 = __float_as_uint(v0), u1 = __float_as_uint(v1);
    hi = __byte_perm(u0, u1, 0x7632);
    float r0 = v0 - __uint_as_float(u0 & 0xFFFF0000u);
    float r1 = v1 - __uint_as_float(u1 & 0xFFFF0000u);
    lo = bf16x2_rn(r0, r1);
}
__device__ __forceinline__ void mma_bf16(float* c, const uint32_t* a, uint32_t b0, uint32_t b1) {
    asm volatile("mma.sync.aligned.m16n8k16.row.col.f32.bf16.bf16.f32 "
        "{%0,%1,%2,%3}, {%4,%5,%6,%7}, {%8,%9}, {%0,%1,%2,%3};"
        : "+f"(c[0]), "+f"(c[1]), "+f"(c[2]), "+f"(c[3])
        : "r"(a[0]), "r"(a[1]), "r"(a[2]), "r"(a[3]), "r"(b0), "r"(b1));
}
__device__ __forceinline__ void ldm_x4(uint32_t addr, uint32_t* r) {
    asm volatile("ldmatrix.sync.aligned.m8n8.x4.shared.b16 {%0,%1,%2,%3}, [%4];"
        : "=r"(r[0]), "=r"(r[1]), "=r"(r[2]), "=r"(r[3]) : "r"(addr));
}
__device__ __forceinline__ uint32_t smem_u32(const void* p) {
    uint32_t a; asm("{ .reg .u64 t; cvta.to.shared.u64 t, %1; cvt.u32.u64 %0, t; }" : "=r"(a) : "l"(p));
    return a;
}

__device__ __forceinline__ int inv_perm(int s) {
    int c2 = s / 6, r = s % 6, j = r >> 1, b = r & 1;
    return (2*c2 + b)*3 + j;
}

__global__ void init_kernel() {
    int t = threadIdx.x;
    if (t < 5) g_maxPre[t]  = 0x007FFFFFu;
    if (t < 4) g_maxPost[t] = 0x007FFFFFu;
}

__device__ __forceinline__ uint4 make_bfrag(float w00, float w01, float w10, float w11) {
    uint32_t u00 = __float_as_uint(w00), u01 = __float_as_uint(w01);
    uint32_t u10 = __float_as_uint(w10), u11 = __float_as_uint(w11);
    uint4 f;
    f.x = __byte_perm(u00, u01, 0x7632);
    f.y = __byte_perm(u10, u11, 0x7632);
    f.z = bf16x2_rn(w00 - __uint_as_float(u00 & 0xFFFF0000u),
                    w01 - __uint_as_float(u01 & 0xFFFF0000u));
    f.w = bf16x2_rn(w10 - __uint_as_float(u10 & 0xFFFF0000u),
                    w11 - __uint_as_float(u11 & 0xFFFF0000u));
    return f;
}

__global__ void prep_weights(const float* __restrict__ w_perc, const float* __restrict__ b_perc,
                             const float* __restrict__ w1, const float* __restrict__ w2,
                             const float* __restrict__ w3) {
    int t = threadIdx.x;
    for (int idx = t; idx < 8*9*9; idx += 256) {
        int c2 = idx / 81, r = idx % 81, dh = r / 9, kk = r % 9, kw = kk / 3, j = kk % 3;
        int kf = dh*3 + kw;
        g_Wq[(c2*9 + dh)*12 + kw*3 + j] =
            pack2(w_perc[((2*c2)*3 + j)*27 + kf], w_perc[((2*c2+1)*3 + j)*27 + kf]);
    }
    if (t < 24) {
        int c2 = t / 3, j = t % 3;
        g_Bpp[t] = pack2(b_perc[(2*c2)*3 + j], b_perc[(2*c2+1)*3 + j]);
    }
    for (int idx = t; idx < 3*8*32; idx += 256) {
        int kt = idx >> 8, n = (idx >> 5) & 7, l = idx & 31;
        int g = l >> 2, q = l & 3, ro = n*8 + g;
        int s0 = kt*16 + 2*q;
        g_Wb1[idx] = make_bfrag(w1[ro*48 + inv_perm(s0)],   w1[ro*48 + inv_perm(s0+1)],
                                w1[ro*48 + inv_perm(s0+8)], w1[ro*48 + inv_perm(s0+9)]);
    }
    for (int idx = t; idx < 4*8*32; idx += 256) {
        int kt = idx >> 8, n = (idx >> 5) & 7, l = idx & 31;
        int g = l >> 2, q = l & 3, ro = n*8 + g;
        int s0 = kt*16 + 2*q;
        g_Wb2[idx] = make_bfrag(w2[ro*64 + s0],   w2[ro*64 + s0+1],
                                w2[ro*64 + s0+8], w2[ro*64 + s0+9]);
    }
    for (int idx = t; idx < 4*2*32; idx += 256) {
        int kt = idx >> 6, n = (idx >> 5) & 1, l = idx & 31;
        int g = l >> 2, q = l & 3, ro = n*8 + g;
        int s0 = kt*16 + 2*q;
        g_Wb3[idx] = make_bfrag(w3[ro*64 + s0],   w3[ro*64 + s0+1],
                                w3[ro*64 + s0+8], w3[ro*64 + s0+9]);
    }
}

__global__ void reduce_ch3_kernel(const float* __restrict__ p) {
    float m = -INFINITY;
    for (int i = blockIdx.x * blockDim.x + threadIdx.x; i < VOL; i += gridDim.x * blockDim.x)
        m = fmaxf(m, p[i]);
    #pragma unroll
    for (int s = 16; s > 0; s >>= 1) m = fmaxf(m, __shfl_xor_sync(0xffffffffu, m, s));
    __shared__ float sm[8];
    if ((threadIdx.x & 31) == 0) sm[threadIdx.x >> 5] = m;
    __syncthreads();
    if (threadIdx.x == 0) {
        int nw = (blockDim.x + 31) / 32;
        float mm = sm[0];
        for (int i = 1; i < nw; i++) mm = fmaxf(mm, sm[i]);
        atomicMax(&g_maxPre[0], encf(mm));
    }
}

// Layer-1 MMA pass from smem (conv activations): 32 rows x 64 outputs, 3 k16-tiles.
__device__ __forceinline__ void mma_pass1(uint32_t rowHi, uint32_t rowLo,
                                          uint32_t xr, uint32_t hi4,
                                          int lane, float C[2][8][4])
{
    #pragma unroll
    for (int m = 0; m < 2; m++)
        #pragma unroll
        for (int n = 0; n < 8; n++)
            #pragma unroll
            for (int i = 0; i < 4; i++) C[m][n][i] = 0.0f;

    #pragma unroll
    for (int k = 0; k < 3; k++) {
        uint32_t off0 = ((2u*k + hi4) ^ xr) << 4;
        uint32_t off1 = ((2u*k + hi4) ^ xr ^ 2u) << 4;   // rows +16: xr flips bit1
        uint32_t h0[4], h1[4], l0[4], l1[4];
        ldm_x4(rowHi + off0, h0);
        ldm_x4(rowHi + 16*SSTR2*2 + off1, h1);
        ldm_x4(rowLo + off0, l0);
        ldm_x4(rowLo + 16*SSTR2*2 + off1, l1);
        #pragma unroll
        for (int n = 0; n < 8; n++) {
            uint4 wf = g_Wb1[(k*8 + n)*32 + lane];
            mma_bf16(C[0][n], h0, wf.x, wf.y);
            mma_bf16(C[0][n], l0, wf.x, wf.y);
            mma_bf16(C[0][n], h0, wf.z, wf.w);
            mma_bf16(C[1][n], h1, wf.x, wf.y);
            mma_bf16(C[1][n], l1, wf.x, wf.y);
            mma_bf16(C[1][n], h1, wf.z, wf.w);
        }
    }
}

// Register-chained layer: Cin[2][8][4] --tanh+bias+split--> MMA --> Cout[2][NT][4]
template<int NT>
__device__ __forceinline__ void mma_chain(const float Cin[2][8][4], const float* sbias,
                                          const uint4* __restrict__ Wf,
                                          int lane, int q, float Cout[2][NT][4])
{
    #pragma unroll
    for (int m = 0; m < 2; m++)
        #pragma unroll
        for (int n = 0; n < NT; n++)
            #pragma unroll
            for (int i = 0; i < 4; i++) Cout[m][n][i] = 0.0f;

    #pragma unroll
    for (int kt = 0; kt < 4; kt++) {
        float b0 = sbias[16*kt + 2*q],     b1 = sbias[16*kt + 2*q + 1];
        float b2 = sbias[16*kt + 8 + 2*q], b3 = sbias[16*kt + 8 + 2*q + 1];
        uint32_t ah[2][4], al[2][4];
        #pragma unroll
        for (int m = 0; m < 2; m++) {
            cvt_frag(Cin[m][2*kt][0],   Cin[m][2*kt][1],   b0, b1, ah[m][0], al[m][0]);
            cvt_frag(Cin[m][2*kt][2],   Cin[m][2*kt][3],   b0, b1, ah[m][1], al[m][1]);
            cvt_frag(Cin[m][2*kt+1][0], Cin[m][2*kt+1][1], b2, b3, ah[m][2], al[m][2]);
            cvt_frag(Cin[m][2*kt+1][2], Cin[m][2*kt+1][3], b2, b3, ah[m][3], al[m][3]);
        }
        #pragma unroll
        for (int n = 0; n < NT; n++) {
            uint4 wf = Wf[(kt*NT + n)*32 + lane];
            mma_bf16(Cout[0][n], ah[0], wf.x, wf.y);
            mma_bf16(Cout[0][n], al[0], wf.x, wf.y);
            mma_bf16(Cout[0][n], ah[0], wf.z, wf.w);
            mma_bf16(Cout[1][n], ah[1], wf.x, wf.y);
            mma_bf16(Cout[1][n], al[1], wf.x, wf.y);
            mma_bf16(Cout[1][n], ah[1], wf.z, wf.w);
        }
    }
}

// Update: block = 192 voxels (2 h-rows), 96 threads (2 voxels each), 3 warps.
__global__ __launch_bounds__(96, 4) void update_kernel(
    const float* __restrict__ xin,
    const float* __restrict__ b1, const float* __restrict__ b2, const float* __restrict__ b3,
    int step)
{
    const float* cur = (step == 0) ? xin : (const float*)g_A;

    extern __shared__ uint16_t SH[];
    uint16_t* Shi = SH;
    uint16_t* Slo = SH + PLANE_H;
    __shared__ float sb1[64], sb2[64], sb3[16];

    const int t = threadIdx.x;
    const int lane = t & 31;
    if (t < 64) { sb1[t] = b1[t]; sb2[t] = b2[t]; }
    if (t < 16) sb3[t] = b3[t];
    __syncthreads();

    const int bb = blockIdx.x * 192;
    const int d  = blockIdx.x / 48;
    const int h0 = (blockIdx.x % 48) * 2;
    const int lv = 2*t;
    const int w0 = lv % 96;
    const int h  = h0 + lv / 96;
    const int p0 = bb + lv;

    const bool vD[3] = { d > 0, true, d < DD-1 };
    const bool vH[3] = { h > 0, true, h < DD-1 };
    const bool wl = (w0 > 0), wr = (w0 < 94);

    // ---- depthwise conv: 2 voxels/thread, edge taps via warp shuffle ----
    {
        float aA = -INFINITY, aB = -INFINITY;
        #pragma unroll 2
        for (int c2 = 0; c2 < 8; c2++) {
            u64t fA0 = g_Bpp[c2*3+0], fA1 = g_Bpp[c2*3+1], fA2 = g_Bpp[c2*3+2];
            u64t fB0 = fA0, fB1 = fA1, fB2 = fA2;
            const float* baseA = cur + (2*c2)*VOL;
            const float* baseB = baseA + VOL;
            #pragma unroll
            for (int kd = 0; kd < 3; kd++)
                #pragma unroll
                for (int kh = 0; kh < 3; kh++) {
                    const bool v = vD[kd] && vH[kh];
                    const int nb = p0 + (kd-1)*PLN + (kh-1)*DD;
                    float2 ca = make_float2(0.0f, 0.0f), cb = make_float2(0.0f, 0.0f);
                    if (v) {
                        ca = *reinterpret_cast<const float2*>(baseA + nb);
                        cb = *reinterpret_cast<const float2*>(baseB + nb);
                    }
                    float ma = __shfl_up_sync(0xffffffffu, ca.y, 1);
                    float mb = __shfl_up_sync(0xffffffffu, cb.y, 1);
                    float pa = __shfl_down_sync(0xffffffffu, ca.x, 1);
                    float pb = __shfl_down_sync(0xffffffffu, cb.x, 1);
                    if (lane == 0 && v && wl)  { ma = baseA[nb-1]; mb = baseB[nb-1]; }
                    if (lane == 31 && v && wr) { pa = baseA[nb+2]; pb = baseB[nb+2]; }
                    if (!wl) { ma = 0.0f; mb = 0.0f; }
                    if (!wr) { pa = 0.0f; pb = 0.0f; }
                    if (c2 == 1 && v) {   // channel 3 (hi lane) alive pool
                        float mx = fmaxf(cb.x, cb.y);
                        aA = fmaxf(aA, mx); if (wl) aA = fmaxf(aA, mb);
                        aB = fmaxf(aB, mx); if (wr) aB = fmaxf(aB, pb);
                    }
                    const ulonglong2* wp2 = reinterpret_cast<const ulonglong2*>(
                        g_Wq + (c2*9 + kd*3 + kh)*12);
                    ulonglong2 q0 = wp2[0], q1 = wp2[1], q2 = wp2[2], q3 = wp2[3];
                    u64t w8 = reinterpret_cast<const u64t*>(wp2)[8];
                    u64t Pm = pack2(ma, mb), Pc0 = pack2(ca.x, cb.x);
                    u64t Pc1 = pack2(ca.y, cb.y), Pp = pack2(pa, pb);
                    fA0 = ffma2(Pm,  q0.x, fA0); fA1 = ffma2(Pm,  q0.y, fA1); fA2 = ffma2(Pm,  q1.x, fA2);
                    fA0 = ffma2(Pc0, q1.y, fA0); fA1 = ffma2(Pc0, q2.x, fA1); fA2 = ffma2(Pc0, q2.y, fA2);
                    fA0 = ffma2(Pc1, q3.x, fA0); fA1 = ffma2(Pc1, q3.y, fA1); fA2 = ffma2(Pc1, w8,   fA2);
                    fB0 = ffma2(Pc0, q0.x, fB0); fB1 = ffma2(Pc0, q0.y, fB1); fB2 = ffma2(Pc0, q1.x, fB2);
                    fB0 = ffma2(Pc1, q1.y, fB0); fB1 = ffma2(Pc1, q2.x, fB1); fB2 = ffma2(Pc1, q2.y, fB2);
                    fB0 = ffma2(Pp,  q3.x, fB0); fB1 = ffma2(Pp,  q3.y, fB1); fB2 = ffma2(Pp,  w8,   fB2);
                }
            float lo, hi;
            unpack2(fA0, lo, hi); st_pair(Shi, Slo, lv,   6*c2+0, lo, hi);
            unpack2(fA1, lo, hi); st_pair(Shi, Slo, lv,   6*c2+2, lo, hi);
            unpack2(fA2, lo, hi); st_pair(Shi, Slo, lv,   6*c2+4, lo, hi);
            unpack2(fB0, lo, hi); st_pair(Shi, Slo, lv+1, 6*c2+0, lo, hi);
            unpack2(fB1, lo, hi); st_pair(Shi, Slo, lv+1, 6*c2+2, lo, hi);
            unpack2(fB2, lo, hi); st_pair(Shi, Slo, lv+1, 6*c2+4, lo, hi);
        }
        *reinterpret_cast<float2*>(&g_alive0[p0]) = make_float2(aA, aB);
    }
    __syncwarp();

    const int wid = t >> 5;
    const int g = lane >> 2, q = lane & 3;
    const uint32_t sbase = smem_u32(Shi);
    const uint32_t hi4 = lane >> 4;
    float m3 = -INFINITY;

    #pragma unroll
    for (int pass = 0; pass < 2; pass++) {
        const int base_r = wid*64 + pass*32;
        const int rr = base_r + (lane & 15);
        const uint32_t xr = ((uint32_t)rr >> 3) & 7u;
        const uint32_t rowHi = sbase + rr*SSTR2*2;
        const uint32_t rowLo = rowHi + PLANE_B;

        // ---- layer 1: 48 -> 64 (from smem) ----
        float C1[2][8][4];
        mma_pass1(rowHi, rowLo, xr, hi4, lane, C1);

        // ---- layer 2: 64 -> 64 (register-chained) ----
        float C2[2][8][4];
        mma_chain<8>(C1, sb1, g_Wb2, lane, q, C2);

        // ---- layer 3: 64 -> 16 (register-chained) ----
        float C3[2][2][4];
        mma_chain<2>(C2, sb2, g_Wb3, lane, q, C3);

        // ---- epilogue: residual + store ----
        #pragma unroll
        for (int m = 0; m < 2; m++) {
            int rA = base_r + m*16 + g;
            int pA = bb + rA, pB = pA + 8;
            #pragma unroll
            for (int n = 0; n < 2; n++) {
                int c0 = 8*n + 2*q, c1 = c0 + 1;
                float v00 = C3[m][n][0] + sb3[c0] + cur[c0*VOL + pA];
                float v01 = C3[m][n][1] + sb3[c1] + cur[c1*VOL + pA];
                float v10 = C3[m][n][2] + sb3[c0] + cur[c0*VOL + pB];
                float v11 = C3[m][n][3] + sb3[c1] + cur[c1*VOL + pB];
                g_B[c0*VOL + pA] = v00;
                g_B[c1*VOL + pA] = v01;
                g_B[c0*VOL + pB] = v10;
                g_B[c1*VOL + pB] = v11;
                if (c1 == 3) m3 = fmaxf(m3, fmaxf(v01, v11));
            }
        }
    }
    #pragma unroll
    for (int s = 16; s > 0; s >>= 1) m3 = fmaxf(m3, __shfl_xor_sync(0xffffffffu, m3, s));
    if (lane == 0) atomicMax(&g_maxPost[step], encf(m3));
}

// Finalize: 4 voxels/thread via float4. Block 96 = 24 w-quads x 4 h-rows; grid (24, 96).
__global__ __launch_bounds__(96) void finalize_kernel(
    float* __restrict__ out, int step, const int* __restrict__ pInOut)
{
    float* dst = (step == 3) ? out : (float*)g_A;

    const int t = threadIdx.x;
    const int wq = t % 24, hr = t / 24;
    const int d = blockIdx.y;
    const int h = blockIdx.x * 4 + hr;
    const int w = wq * 4;
    const int pos = d*PLN + h*DD + w;

    const bool vD[3] = { d > 0, true, d < DD-1 };
    const bool vH[3] = { h > 0, true, h < DD-1 };
    const bool wl = (w > 0), wr = (w < 92);

    const float* B3 = g_B + 3*VOL;
    float4 m4 = make_float4(-INFINITY, -INFINITY, -INFINITY, -INFINITY);
    float eL = -INFINITY, eR = -INFINITY;
    #pragma unroll
    for (int kd = 0; kd < 3; kd++)
        #pragma unroll
        for (int kh = 0; kh < 3; kh++)
            if (vD[kd] && vH[kh]) {
                int nb = pos + (kd-1)*PLN + (kh-1)*DD;
                float4 r = *reinterpret_cast<const float4*>(B3 + nb);
                m4.x = fmaxf(m4.x, r.x); m4.y = fmaxf(m4.y, r.y);
                m4.z = fmaxf(m4.z, r.z); m4.w = fmaxf(m4.w, r.w);
                if (wl) eL = fmaxf(eL, B3[nb-1]);
                if (wr) eR = fmaxf(eR, B3[nb+4]);
            }
    float m1_0 = fmaxf(fmaxf(eL,   m4.x), m4.y);
    float m1_1 = fmaxf(fmaxf(m4.x, m4.y), m4.z);
    float m1_2 = fmaxf(fmaxf(m4.y, m4.z), m4.w);
    float m1_3 = fmaxf(fmaxf(m4.z, m4.w), eR);

    float th0 = 0.1f * decf(g_maxPre[step]);  if (isnan(th0)) th0 = -INFINITY;
    float th1 = 0.1f * decf(g_maxPost[step]); if (isnan(th1)) th1 = -INFINITY;

    float4 a0 = *reinterpret_cast<const float4*>(g_alive0 + pos);
    bool zero = (d == DD-1) && (h >= *pInOut);
    float lf0 = (!zero && a0.x > th0 && m1_0 > th1) ? 1.0f : 0.0f;
    float lf1 = (!zero && a0.y > th0 && m1_1 > th1) ? 1.0f : 0.0f;
    float lf2 = (!zero && a0.z > th0 && m1_2 > th1) ? 1.0f : 0.0f;
    float lf3 = (!zero && a0.w > th0 && m1_3 > th1) ? 1.0f : 0.0f;

    float v3 = -INFINITY;
    #pragma unroll
    for (int c = 0; c < NC; c++) {
        float4 v = *reinterpret_cast<const float4*>(g_B + c*VOL + pos);
        v.x *= lf0; v.y *= lf1; v.z *= lf2; v.w *= lf3;
        *reinterpret_cast<float4*>(dst + c*VOL + pos) = v;
        if (c == 3) v3 = fmaxf(fmaxf(v.x, v.y), fmaxf(v.z, v.w));
    }

    #pragma unroll
    for (int s = 16; s > 0; s >>= 1) v3 = fmaxf(v3, __shfl_xor_sync(0xffffffffu, v3, s));
    if ((t & 31) == 0) atomicMax(&g_maxPre[step + 1], encf(v3));
}

extern "C" void kernel_launch(void* const* d_in, const int* in_sizes, int n_in,
                              void* d_out, int out_size) {
    (void)in_sizes; (void)n_in; (void)out_size;
    const float* x      = (const float*)d_in[0];
    const float* w_perc = (const float*)d_in[1];
    const float* b_perc = (const float*)d_in[2];
    const float* w1     = (const float*)d_in[3];
    const float* b1     = (const float*)d_in[4];
    const float* w2     = (const float*)d_in[5];
    const float* b2     = (const float*)d_in[6];
    const float* w3     = (const float*)d_in[7];
    const float* b3     = (const float*)d_in[8];
    const int*   pInOut = (const int*)d_in[12];
    float* out = (float*)d_out;

    static bool attr_set = false;
    if (!attr_set) {
        cudaFuncSetAttribute(update_kernel, cudaFuncAttributeMaxDynamicSharedMemorySize, SMEM_BYTES);
        attr_set = true;
    }

    init_kernel<<<1, 32>>>();
    prep_weights<<<1, 256>>>(w_perc, b_perc, w1, w2, w3);
    reduce_ch3_kernel<<<432, 256>>>(x + 3*VOL);

    dim3 fgrd(24, DD);
    for (int s = 0; s < 4; s++) {
        update_kernel<<<VOL/192, 96, SMEM_BYTES>>>(x, b1, b2, b3, s);
        finalize_kernel<<<fgrd, 96>>>(out, s, pInOut);
    }
}

// round 16
// speedup vs baseline: 1.2782x; 1.0045x over previous
#include <cuda_runtime.h>
#include <math.h>
#include <stdint.h>

#define DD  96
#define PLN (DD*DD)
#define VOL (DD*DD*DD)
#define NC  16
#define NTILES (VOL/192)             // 4608
#define NBLK   592                   // 148 SMs x 4 blocks
#define SSTR2 72                     // S row stride in bf16 halves (144B)
#define PLANE_H (192*SSTR2)          // halves per plane (13824)
#define PLANE_B (PLANE_H*2)          // 27648 bytes
#define SMEM_BYTES (2*PLANE_B)       // 55296

__device__ __align__(16) float g_A[NC*VOL];
__device__ __align__(16) float g_B[NC*VOL];
__device__ __align__(16) float g_alive0[VOL];
__device__ unsigned g_maxPre[5];
__device__ unsigned g_maxPost[4];

typedef unsigned long long u64t;
__device__ __align__(16) u64t  g_Wq[8*9*12];        // conv weight pairs, padded
__device__ u64t  g_Bpp[24];                          // conv bias pairs
__device__ __align__(16) uint4 g_Wb1[3*8*32];        // bf16 hi/lo B-frags (K perm applied)
__device__ __align__(16) uint4 g_Wb2[4*8*32];
__device__ __align__(16) uint4 g_Wb3[4*2*32];

__device__ __forceinline__ unsigned encf(float f) {
    unsigned u = __float_as_uint(f);
    return (u & 0x80000000u) ? ~u : (u | 0x80000000u);
}
__device__ __forceinline__ float decf(unsigned e) {
    return __uint_as_float((e & 0x80000000u) ? (e ^ 0x80000000u) : ~e);
}
__device__ __forceinline__ float tanh_fast(float x) {
    float y; asm("tanh.approx.f32 %0, %1;" : "=f"(y) : "f"(x)); return y;
}
__device__ __forceinline__ u64t pack2(float lo, float hi) {
    u64t r; asm("mov.b64 %0, {%1, %2};" : "=l"(r) : "f"(lo), "f"(hi)); return r;
}
__device__ __forceinline__ void unpack2(u64t v, float& lo, float& hi) {
    asm("mov.b64 {%0, %1}, %2;" : "=f"(lo), "=f"(hi) : "l"(v));
}
__device__ __forceinline__ u64t ffma2(u64t a, u64t b, u64t c) {
    u64t d; asm("fma.rn.f32x2 %0, %1, %2, %3;" : "=l"(d) : "l"(a), "l"(b), "l"(c)); return d;
}
__device__ __forceinline__ uint32_t bf16x2_rn(float f0, float f1) {
    uint32_t r;  // {low=bf16(f0), high=bf16(f1)}
    asm("cvt.rn.bf16x2.f32 %0, %1, %2;" : "=r"(r) : "f"(f1), "f"(f0));
    return r;
}
// store fp32 pair (cols col, col+1) as hi/lo bf16 planes, XOR-swizzled 16B chunks
__device__ __forceinline__ void st_pair(uint16_t* Shi, uint16_t* Slo, int row, int col,
                                        float f0, float f1) {
    uint32_t u0 = __float_as_uint(f0), u1 = __float_as_uint(f1);
    uint32_t hp = __byte_perm(u0, u1, 0x7632);           // {hi16(f0), hi16(f1)}
    float r0 = f0 - __uint_as_float(u0 & 0xFFFF0000u);   // exact residual
    float r1 = f1 - __uint_as_float(u1 & 0xFFFF0000u);
    uint32_t lp = bf16x2_rn(r0, r1);
    int chunk = (col >> 3) ^ ((row >> 3) & 7);
    int idx = row*SSTR2 + (chunk << 3) + (col & 7);
    *(uint32_t*)&Shi[idx] = hp;
    *(uint32_t*)&Slo[idx] = lp;
}
// tanh(c + b) pair -> bf16 hi/lo frag registers (same rounding as st_pair path)
__device__ __forceinline__ void cvt_frag(float c0, float c1, float b0v, float b1v,
                                         uint32_t& hi, uint32_t& lo) {
    float v0 = tanh_fast(c0 + b0v), v1 = tanh_fast(c1 + b1v);
    uint32_t u0 = __float_as_uint(v0), u1 = __float_as_uint(v1);
    hi = __byte_perm(u0, u1, 0x7632);
    float r0 = v0 - __uint_as_float(u0 & 0xFFFF0000u);
    float r1 = v1 - __uint_as_float(u1 & 0xFFFF0000u);
    lo = bf16x2_rn(r0, r1);
}
__device__ __forceinline__ void mma_bf16(float* c, const uint32_t* a, uint32_t b0, uint32_t b1) {
    asm volatile("mma.sync.aligned.m16n8k16.row.col.f32.bf16.bf16.f32 "
        "{%0,%1,%2,%3}, {%4,%5,%6,%7}, {%8,%9}, {%0,%1,%2,%3};"
        : "+f"(c[0]), "+f"(c[1]), "+f"(c[2]), "+f"(c[3])
        : "r"(a[0]), "r"(a[1]), "r"(a[2]), "r"(a[3]), "r"(b0), "r"(b1));
}
__device__ __forceinline__ void ldm_x4(uint32_t addr, uint32_t* r) {
    asm volatile("ldmatrix.sync.aligned.m8n8.x4.shared.b16 {%0,%1,%2,%3}, [%4];"
        : "=r"(r[0]), "=r"(r[1]), "=r"(r[2]), "=r"(r[3]) : "r"(addr));
}
__device__ __forceinline__ uint32_t smem_u32(const void* p) {
    uint32_t a; asm("{ .reg .u64 t; cvta.to.shared.u64 t, %1; cvt.u32.u64 %0, t; }" : "=r"(a) : "l"(p));
    return a;
}

__device__ __forceinline__ int inv_perm(int s) {
    int c2 = s / 6, r = s % 6, j = r >> 1, b = r & 1;
    return (2*c2 + b)*3 + j;
}

__global__ void init_kernel() {
    int t = threadIdx.x;
    if (t < 5) g_maxPre[t]  = 0x007FFFFFu;
    if (t < 4) g_maxPost[t] = 0x007FFFFFu;
}

__device__ __forceinline__ uint4 make_bfrag(float w00, float w01, float w10, float w11) {
    uint32_t u00 = __float_as_uint(w00), u01 = __float_as_uint(w01);
    uint32_t u10 = __float_as_uint(w10), u11 = __float_as_uint(w11);
    uint4 f;
    f.x = __byte_perm(u00, u01, 0x7632);
    f.y = __byte_perm(u10, u11, 0x7632);
    f.z = bf16x2_rn(w00 - __uint_as_float(u00 & 0xFFFF0000u),
                    w01 - __uint_as_float(u01 & 0xFFFF0000u));
    f.w = bf16x2_rn(w10 - __uint_as_float(u10 & 0xFFFF0000u),
                    w11 - __uint_as_float(u11 & 0xFFFF0000u));
    return f;
}

__global__ void prep_weights(const float* __restrict__ w_perc, const float* __restrict__ b_perc,
                             const float* __restrict__ w1, const float* __restrict__ w2,
                             const float* __restrict__ w3) {
    int t = threadIdx.x;
    for (int idx = t; idx < 8*9*9; idx += 256) {
        int c2 = idx / 81, r = idx % 81, dh = r / 9, kk = r % 9, kw = kk / 3, j = kk % 3;
        int kf = dh*3 + kw;
        g_Wq[(c2*9 + dh)*12 + kw*3 + j] =
            pack2(w_perc[((2*c2)*3 + j)*27 + kf], w_perc[((2*c2+1)*3 + j)*27 + kf]);
    }
    if (t < 24) {
        int c2 = t / 3, j = t % 3;
        g_Bpp[t] = pack2(b_perc[(2*c2)*3 + j], b_perc[(2*c2+1)*3 + j]);
    }
    for (int idx = t; idx < 3*8*32; idx += 256) {
        int kt = idx >> 8, n = (idx >> 5) & 7, l = idx & 31;
        int g = l >> 2, q = l & 3, ro = n*8 + g;
        int s0 = kt*16 + 2*q;
        g_Wb1[idx] = make_bfrag(w1[ro*48 + inv_perm(s0)],   w1[ro*48 + inv_perm(s0+1)],
                                w1[ro*48 + inv_perm(s0+8)], w1[ro*48 + inv_perm(s0+9)]);
    }
    for (int idx = t; idx < 4*8*32; idx += 256) {
        int kt = idx >> 8, n = (idx >> 5) & 7, l = idx & 31;
        int g = l >> 2, q = l & 3, ro = n*8 + g;
        int s0 = kt*16 + 2*q;
        g_Wb2[idx] = make_bfrag(w2[ro*64 + s0],   w2[ro*64 + s0+1],
                                w2[ro*64 + s0+8], w2[ro*64 + s0+9]);
    }
    for (int idx = t; idx < 4*2*32; idx += 256) {
        int kt = idx >> 6, n = (idx >> 5) & 1, l = idx & 31;
        int g = l >> 2, q = l & 3, ro = n*8 + g;
        int s0 = kt*16 + 2*q;
        g_Wb3[idx] = make_bfrag(w3[ro*64 + s0],   w3[ro*64 + s0+1],
                                w3[ro*64 + s0+8], w3[ro*64 + s0+9]);
    }
}

__global__ void reduce_ch3_kernel(const float* __restrict__ p) {
    float m = -INFINITY;
    for (int i = blockIdx.x * blockDim.x + threadIdx.x; i < VOL; i += gridDim.x * blockDim.x)
        m = fmaxf(m, p[i]);
    #pragma unroll
    for (int s = 16; s > 0; s >>= 1) m = fmaxf(m, __shfl_xor_sync(0xffffffffu, m, s));
    __shared__ float sm[8];
    if ((threadIdx.x & 31) == 0) sm[threadIdx.x >> 5] = m;
    __syncthreads();
    if (threadIdx.x == 0) {
        int nw = (blockDim.x + 31) / 32;
        float mm = sm[0];
        for (int i = 1; i < nw; i++) mm = fmaxf(mm, sm[i]);
        atomicMax(&g_maxPre[0], encf(mm));
    }
}

// Layer-1 MMA pass from smem (conv activations): 32 rows x 64 outputs, 3 k16-tiles.
__device__ __forceinline__ void mma_pass1(uint32_t rowHi, uint32_t rowLo,
                                          uint32_t xr, uint32_t hi4,
                                          int lane, float C[2][8][4])
{
    #pragma unroll
    for (int m = 0; m < 2; m++)
        #pragma unroll
        for (int n = 0; n < 8; n++)
            #pragma unroll
            for (int i = 0; i < 4; i++) C[m][n][i] = 0.0f;

    #pragma unroll
    for (int k = 0; k < 3; k++) {
        uint32_t off0 = ((2u*k + hi4) ^ xr) << 4;
        uint32_t off1 = ((2u*k + hi4) ^ xr ^ 2u) << 4;   // rows +16: xr flips bit1
        uint32_t h0[4], h1[4], l0[4], l1[4];
        ldm_x4(rowHi + off0, h0);
        ldm_x4(rowHi + 16*SSTR2*2 + off1, h1);
        ldm_x4(rowLo + off0, l0);
        ldm_x4(rowLo + 16*SSTR2*2 + off1, l1);
        #pragma unroll
        for (int n = 0; n < 8; n++) {
            uint4 wf = g_Wb1[(k*8 + n)*32 + lane];
            mma_bf16(C[0][n], h0, wf.x, wf.y);
            mma_bf16(C[0][n], l0, wf.x, wf.y);
            mma_bf16(C[0][n], h0, wf.z, wf.w);
            mma_bf16(C[1][n], h1, wf.x, wf.y);
            mma_bf16(C[1][n], l1, wf.x, wf.y);
            mma_bf16(C[1][n], h1, wf.z, wf.w);
        }
    }
}

// Register-chained layer: Cin[2][8][4] --tanh+bias+split--> MMA --> Cout[2][NT][4]
template<int NT>
__device__ __forceinline__ void mma_chain(const float Cin[2][8][4], const float* sbias,
                                          const uint4* __restrict__ Wf,
                                          int lane, int q, float Cout[2][NT][4])
{
    #pragma unroll
    for (int m = 0; m < 2; m++)
        #pragma unroll
        for (int n = 0; n < NT; n++)
            #pragma unroll
            for (int i = 0; i < 4; i++) Cout[m][n][i] = 0.0f;

    #pragma unroll
    for (int kt = 0; kt < 4; kt++) {
        float b0 = sbias[16*kt + 2*q],     b1 = sbias[16*kt + 2*q + 1];
        float b2 = sbias[16*kt + 8 + 2*q], b3 = sbias[16*kt + 8 + 2*q + 1];
        uint32_t ah[2][4], al[2][4];
        #pragma unroll
        for (int m = 0; m < 2; m++) {
            cvt_frag(Cin[m][2*kt][0],   Cin[m][2*kt][1],   b0, b1, ah[m][0], al[m][0]);
            cvt_frag(Cin[m][2*kt][2],   Cin[m][2*kt][3],   b0, b1, ah[m][1], al[m][1]);
            cvt_frag(Cin[m][2*kt+1][0], Cin[m][2*kt+1][1], b2, b3, ah[m][2], al[m][2]);
            cvt_frag(Cin[m][2*kt+1][2], Cin[m][2*kt+1][3], b2, b3, ah[m][3], al[m][3]);
        }
        #pragma unroll
        for (int n = 0; n < NT; n++) {
            uint4 wf = Wf[(kt*NT + n)*32 + lane];
            mma_bf16(Cout[0][n], ah[0], wf.x, wf.y);
            mma_bf16(Cout[0][n], al[0], wf.x, wf.y);
            mma_bf16(Cout[0][n], ah[0], wf.z, wf.w);
            mma_bf16(Cout[1][n], ah[1], wf.x, wf.y);
            mma_bf16(Cout[1][n], al[1], wf.x, wf.y);
            mma_bf16(Cout[1][n], ah[1], wf.z, wf.w);
        }
    }
}

// Persistent update: 592 blocks, each strides over tiles. Block tile = 192 voxels
// (2 h-rows), 96 threads (2 voxels each), 3 warps; warp-private smem rows.
__global__ __launch_bounds__(96, 4) void update_kernel(
    const float* __restrict__ xin,
    const float* __restrict__ b1, const float* __restrict__ b2, const float* __restrict__ b3,
    int step)
{
    const float* cur = (step == 0) ? xin : (const float*)g_A;

    extern __shared__ uint16_t SH[];
    uint16_t* Shi = SH;
    uint16_t* Slo = SH + PLANE_H;
    __shared__ float sb1[64], sb2[64], sb3[16];

    const int t = threadIdx.x;
    const int lane = t & 31;
    if (t < 64) { sb1[t] = b1[t]; sb2[t] = b2[t]; }
    if (t < 16) sb3[t] = b3[t];
    __syncthreads();

    const int wid = t >> 5;
    const int g = lane >> 2, q = lane & 3;
    const uint32_t sbase = smem_u32(Shi);
    const uint32_t hi4 = lane >> 4;
    float mPost = -INFINITY;

    for (int tile = blockIdx.x; tile < NTILES; tile += NBLK) {
        const int bb = tile * 192;
        const int d  = tile / 48;
        const int h0 = (tile % 48) * 2;
        const int lv = 2*t;
        const int w0 = lv % 96;
        const int h  = h0 + lv / 96;
        const int p0 = bb + lv;

        const bool vD[3] = { d > 0, true, d < DD-1 };
        const bool vH[3] = { h > 0, true, h < DD-1 };
        const bool wl = (w0 > 0), wr = (w0 < 94);

        // ---- depthwise conv: 2 voxels/thread, edge taps via warp shuffle ----
        {
            float aA = -INFINITY, aB = -INFINITY;
            #pragma unroll 2
            for (int c2 = 0; c2 < 8; c2++) {
                u64t fA0 = g_Bpp[c2*3+0], fA1 = g_Bpp[c2*3+1], fA2 = g_Bpp[c2*3+2];
                u64t fB0 = fA0, fB1 = fA1, fB2 = fA2;
                const float* baseA = cur + (2*c2)*VOL;
                const float* baseB = baseA + VOL;
                #pragma unroll
                for (int kd = 0; kd < 3; kd++)
                    #pragma unroll
                    for (int kh = 0; kh < 3; kh++) {
                        const bool v = vD[kd] && vH[kh];
                        const int nb = p0 + (kd-1)*PLN + (kh-1)*DD;
                        float2 ca = make_float2(0.0f, 0.0f), cb = make_float2(0.0f, 0.0f);
                        if (v) {
                            ca = *reinterpret_cast<const float2*>(baseA + nb);
                            cb = *reinterpret_cast<const float2*>(baseB + nb);
                        }
                        float ma = __shfl_up_sync(0xffffffffu, ca.y, 1);
                        float mb = __shfl_up_sync(0xffffffffu, cb.y, 1);
                        float pa = __shfl_down_sync(0xffffffffu, ca.x, 1);
                        float pb = __shfl_down_sync(0xffffffffu, cb.x, 1);
                        if (lane == 0 && v && wl)  { ma = baseA[nb-1]; mb = baseB[nb-1]; }
                        if (lane == 31 && v && wr) { pa = baseA[nb+2]; pb = baseB[nb+2]; }
                        if (!wl) { ma = 0.0f; mb = 0.0f; }
                        if (!wr) { pa = 0.0f; pb = 0.0f; }
                        if (c2 == 1 && v) {   // channel 3 (hi lane) alive pool
                            float mx = fmaxf(cb.x, cb.y);
                            aA = fmaxf(aA, mx); if (wl) aA = fmaxf(aA, mb);
                            aB = fmaxf(aB, mx); if (wr) aB = fmaxf(aB, pb);
                        }
                        const ulonglong2* wp2 = reinterpret_cast<const ulonglong2*>(
                            g_Wq + (c2*9 + kd*3 + kh)*12);
                        ulonglong2 q0 = wp2[0], q1 = wp2[1], q2 = wp2[2], q3 = wp2[3];
                        u64t w8 = reinterpret_cast<const u64t*>(wp2)[8];
                        u64t Pm = pack2(ma, mb), Pc0 = pack2(ca.x, cb.x);
                        u64t Pc1 = pack2(ca.y, cb.y), Pp = pack2(pa, pb);
                        fA0 = ffma2(Pm,  q0.x, fA0); fA1 = ffma2(Pm,  q0.y, fA1); fA2 = ffma2(Pm,  q1.x, fA2);
                        fA0 = ffma2(Pc0, q1.y, fA0); fA1 = ffma2(Pc0, q2.x, fA1); fA2 = ffma2(Pc0, q2.y, fA2);
                        fA0 = ffma2(Pc1, q3.x, fA0); fA1 = ffma2(Pc1, q3.y, fA1); fA2 = ffma2(Pc1, w8,   fA2);
                        fB0 = ffma2(Pc0, q0.x, fB0); fB1 = ffma2(Pc0, q0.y, fB1); fB2 = ffma2(Pc0, q1.x, fB2);
                        fB0 = ffma2(Pc1, q1.y, fB0); fB1 = ffma2(Pc1, q2.x, fB1); fB2 = ffma2(Pc1, q2.y, fB2);
                        fB0 = ffma2(Pp,  q3.x, fB0); fB1 = ffma2(Pp,  q3.y, fB1); fB2 = ffma2(Pp,  w8,   fB2);
                    }
                float lo, hi;
                unpack2(fA0, lo, hi); st_pair(Shi, Slo, lv,   6*c2+0, lo, hi);
                unpack2(fA1, lo, hi); st_pair(Shi, Slo, lv,   6*c2+2, lo, hi);
                unpack2(fA2, lo, hi); st_pair(Shi, Slo, lv,   6*c2+4, lo, hi);
                unpack2(fB0, lo, hi); st_pair(Shi, Slo, lv+1, 6*c2+0, lo, hi);
                unpack2(fB1, lo, hi); st_pair(Shi, Slo, lv+1, 6*c2+2, lo, hi);
                unpack2(fB2, lo, hi); st_pair(Shi, Slo, lv+1, 6*c2+4, lo, hi);
            }
            *reinterpret_cast<float2*>(&g_alive0[p0]) = make_float2(aA, aB);
        }
        __syncwarp();

        #pragma unroll
        for (int pass = 0; pass < 2; pass++) {
            const int base_r = wid*64 + pass*32;
            const int rr = base_r + (lane & 15);
            const uint32_t xr = ((uint32_t)rr >> 3) & 7u;
            const uint32_t rowHi = sbase + rr*SSTR2*2;
            const uint32_t rowLo = rowHi + PLANE_B;

            // layer 1 (smem), layers 2+3 register-chained
            float C1[2][8][4];
            mma_pass1(rowHi, rowLo, xr, hi4, lane, C1);
            float C2[2][8][4];
            mma_chain<8>(C1, sb1, g_Wb2, lane, q, C2);
            float C3[2][2][4];
            mma_chain<2>(C2, sb2, g_Wb3, lane, q, C3);

            // epilogue: residual + store
            #pragma unroll
            for (int m = 0; m < 2; m++) {
                int rA = base_r + m*16 + g;
                int pA = bb + rA, pB = pA + 8;
                #pragma unroll
                for (int n = 0; n < 2; n++) {
                    int c0 = 8*n + 2*q, c1 = c0 + 1;
                    float v00 = C3[m][n][0] + sb3[c0] + __ldg(&cur[c0*VOL + pA]);
                    float v01 = C3[m][n][1] + sb3[c1] + __ldg(&cur[c1*VOL + pA]);
                    float v10 = C3[m][n][2] + sb3[c0] + __ldg(&cur[c0*VOL + pB]);
                    float v11 = C3[m][n][3] + sb3[c1] + __ldg(&cur[c1*VOL + pB]);
                    g_B[c0*VOL + pA] = v00;
                    g_B[c1*VOL + pA] = v01;
                    g_B[c0*VOL + pB] = v10;
                    g_B[c1*VOL + pB] = v11;
                    if (c1 == 3) mPost = fmaxf(mPost, fmaxf(v01, v11));
                }
            }
        }
        __syncwarp();
    }

    #pragma unroll
    for (int s = 16; s > 0; s >>= 1) mPost = fmaxf(mPost, __shfl_xor_sync(0xffffffffu, mPost, s));
    if (lane == 0) atomicMax(&g_maxPost[step], encf(mPost));
}

// Finalize: 4 voxels/thread via float4. Block 96 = 24 w-quads x 4 h-rows; grid (24, 96).
__global__ __launch_bounds__(96) void finalize_kernel(
    float* __restrict__ out, int step, const int* __restrict__ pInOut)
{
    float* dst = (step == 3) ? out : (float*)g_A;

    const int t = threadIdx.x;
    const int wq = t % 24, hr = t / 24;
    const int d = blockIdx.y;
    const int h = blockIdx.x * 4 + hr;
    const int w = wq * 4;
    const int pos = d*PLN + h*DD + w;

    const bool vD[3] = { d > 0, true, d < DD-1 };
    const bool vH[3] = { h > 0, true, h < DD-1 };
    const bool wl = (w > 0), wr = (w < 92);

    const float* B3 = g_B + 3*VOL;
    float4 m4 = make_float4(-INFINITY, -INFINITY, -INFINITY, -INFINITY);
    float eL = -INFINITY, eR = -INFINITY;
    #pragma unroll
    for (int kd = 0; kd < 3; kd++)
        #pragma unroll
        for (int kh = 0; kh < 3; kh++)
            if (vD[kd] && vH[kh]) {
                int nb = pos + (kd-1)*PLN + (kh-1)*DD;
                float4 r = *reinterpret_cast<const float4*>(B3 + nb);
                m4.x = fmaxf(m4.x, r.x); m4.y = fmaxf(m4.y, r.y);
                m4.z = fmaxf(m4.z, r.z); m4.w = fmaxf(m4.w, r.w);
                if (wl) eL = fmaxf(eL, B3[nb-1]);
                if (wr) eR = fmaxf(eR, B3[nb+4]);
            }
    float m1_0 = fmaxf(fmaxf(eL,   m4.x), m4.y);
    float m1_1 = fmaxf(fmaxf(m4.x, m4.y), m4.z);
    float m1_2 = fmaxf(fmaxf(m4.y, m4.z), m4.w);
    float m1_3 = fmaxf(fmaxf(m4.z, m4.w), eR);

    float th0 = 0.1f * decf(g_maxPre[step]);  if (isnan(th0)) th0 = -INFINITY;
    float th1 = 0.1f * decf(g_maxPost[step]); if (isnan(th1)) th1 = -INFINITY;

    float4 a0 = *reinterpret_cast<const float4*>(g_alive0 + pos);
    bool zero = (d == DD-1) && (h >= *pInOut);
    float lf0 = (!zero && a0.x > th0 && m1_0 > th1) ? 1.0f : 0.0f;
    float lf1 = (!zero && a0.y > th0 && m1_1 > th1) ? 1.0f : 0.0f;
    float lf2 = (!zero && a0.z > th0 && m1_2 > th1) ? 1.0f : 0.0f;
    float lf3 = (!zero && a0.w > th0 && m1_3 > th1) ? 1.0f : 0.0f;

    float v3 = -INFINITY;
    #pragma unroll
    for (int c = 0; c < NC; c++) {
        float4 v = *reinterpret_cast<const float4*>(g_B + c*VOL + pos);
        v.x *= lf0; v.y *= lf1; v.z *= lf2; v.w *= lf3;
        *reinterpret_cast<float4*>(dst + c*VOL + pos) = v;
        if (c == 3) v3 = fmaxf(fmaxf(v.x, v.y), fmaxf(v.z, v.w));
    }

    #pragma unroll
    for (int s = 16; s > 0; s >>= 1) v3 = fmaxf(v3, __shfl_xor_sync(0xffffffffu, v3, s));
    if ((t & 31) == 0) atomicMax(&g_maxPre[step + 1], encf(v3));
}

extern "C" void kernel_launch(void* const* d_in, const int* in_sizes, int n_in,
                              void* d_out, int out_size) {
    (void)in_sizes; (void)n_in; (void)out_size;
    const float* x      = (const float*)d_in[0];
    const float* w_perc = (const float*)d_in[1];
    const float* b_perc = (const float*)d_in[2];
    const float* w1     = (const float*)d_in[3];
    const float* b1     = (const float*)d_in[4];
    const float* w2     = (const float*)d_in[5];
    const float* b2     = (const float*)d_in[6];
    const float* w3     = (const float*)d_in[7];
    const float* b3     = (const float*)d_in[8];
    const int*   pInOut = (const int*)d_in[12];
    float* out = (float*)d_out;

    static bool attr_set = false;
    if (!attr_set) {
        cudaFuncSetAttribute(update_kernel, cudaFuncAttributeMaxDynamicSharedMemorySize, SMEM_BYTES);
        attr_set = true;
    }

    init_kernel<<<1, 32>>>();
    prep_weights<<<1, 256>>>(w_perc, b_perc, w1, w2, w3);
    reduce_ch3_kernel<<<432, 256>>>(x + 3*VOL);

    dim3 fgrd(24, DD);
    for (int s = 0; s < 4; s++) {
        update_kernel<<<NBLK, 96, SMEM_BYTES>>>(x, b1, b2, b3, s);
        finalize_kernel<<<fgrd, 96>>>(out, s, pInOut);
    }
}

// round 17
// speedup vs baseline: 1.3468x; 1.0536x over previous
#include <cuda_runtime.h>
#include <math.h>
#include <stdint.h>

#define DD  96
#define PLN (DD*DD)
#define VOL (DD*DD*DD)
#define NC  16
#define NTILES (VOL/192)             // 4608
#define NBLK   592                   // 148 SMs x 4 blocks
#define SSTR2 72                     // S row stride in bf16 halves (144B)
#define PLANE_H (192*SSTR2)          // halves per plane (13824)
#define PLANE_B (PLANE_H*2)          // 27648 bytes
#define SMEM_BYTES (2*PLANE_B)       // 55296

__device__ __align__(16) float g_A[NC*VOL];
__device__ __align__(16) float g_B[NC*VOL];
__device__ __align__(16) float g_alive0[VOL];
__device__ unsigned g_maxPre[5];
__device__ unsigned g_maxPost[4];

typedef unsigned long long u64t;
__device__ __align__(16) u64t  g_Wq[8*9*12];        // conv weight pairs, padded
__device__ u64t  g_Bpp[24];                          // conv bias pairs
__device__ __align__(16) uint4 g_Wb1[3*8*32];        // bf16 hi/lo B-frags (K perm applied)
__device__ __align__(16) uint4 g_Wb2[4*8*32];
__device__ __align__(16) uint4 g_Wb3[4*2*32];

__device__ __forceinline__ unsigned encf(float f) {
    unsigned u = __float_as_uint(f);
    return (u & 0x80000000u) ? ~u : (u | 0x80000000u);
}
__device__ __forceinline__ float decf(unsigned e) {
    return __uint_as_float((e & 0x80000000u) ? (e ^ 0x80000000u) : ~e);
}
__device__ __forceinline__ float tanh_fast(float x) {
    float y; asm("tanh.approx.f32 %0, %1;" : "=f"(y) : "f"(x)); return y;
}
__device__ __forceinline__ u64t pack2(float lo, float hi) {
    u64t r; asm("mov.b64 %0, {%1, %2};" : "=l"(r) : "f"(lo), "f"(hi)); return r;
}
__device__ __forceinline__ void unpack2(u64t v, float& lo, float& hi) {
    asm("mov.b64 {%0, %1}, %2;" : "=f"(lo), "=f"(hi) : "l"(v));
}
__device__ __forceinline__ u64t ffma2(u64t a, u64t b, u64t c) {
    u64t d; asm("fma.rn.f32x2 %0, %1, %2, %3;" : "=l"(d) : "l"(a), "l"(b), "l"(c)); return d;
}
__device__ __forceinline__ uint32_t bf16x2_rn(float f0, float f1) {
    uint32_t r;  // {low=bf16(f0), high=bf16(f1)}
    asm("cvt.rn.bf16x2.f32 %0, %1, %2;" : "=r"(r) : "f"(f1), "f"(f0));
    return r;
}
// store fp32 pair (cols col, col+1) as hi/lo bf16 planes, XOR-swizzled 16B chunks.
// Chunks 0..7 (halves 0..63) only; halves 64..71 are the weight stash.
__device__ __forceinline__ void st_pair(uint16_t* Shi, uint16_t* Slo, int row, int col,
                                        float f0, float f1) {
    uint32_t u0 = __float_as_uint(f0), u1 = __float_as_uint(f1);
    uint32_t hp = __byte_perm(u0, u1, 0x7632);           // {hi16(f0), hi16(f1)}
    float r0 = f0 - __uint_as_float(u0 & 0xFFFF0000u);   // exact residual
    float r1 = f1 - __uint_as_float(u1 & 0xFFFF0000u);
    uint32_t lp = bf16x2_rn(r0, r1);
    int chunk = (col >> 3) ^ ((row >> 3) & 7);
    int idx = row*SSTR2 + (chunk << 3) + (col & 7);
    *(uint32_t*)&Shi[idx] = hp;
    *(uint32_t*)&Slo[idx] = lp;
}
// tanh(c + b) pair -> bf16 hi/lo frag registers (same rounding as st_pair path)
__device__ __forceinline__ void cvt_frag(float c0, float c1, float b0v, float b1v,
                                         uint32_t& hi, uint32_t& lo) {
    float v0 = tanh_fast(c0 + b0v), v1 = tanh_fast(c1 + b1v);
    uint32_t u0 = __float_as_uint(v0), u1 = __float_as_uint(v1);
    hi = __byte_perm(u0, u1, 0x7632);
    float r0 = v0 - __uint_as_float(u0 & 0xFFFF0000u);
    float r1 = v1 - __uint_as_float(u1 & 0xFFFF0000u);
    lo = bf16x2_rn(r0, r1);
}
__device__ __forceinline__ void mma_bf16(float* c, const uint32_t* a, uint32_t b0, uint32_t b1) {
    asm volatile("mma.sync.aligned.m16n8k16.row.col.f32.bf16.bf16.f32 "
        "{%0,%1,%2,%3}, {%4,%5,%6,%7}, {%8,%9}, {%0,%1,%2,%3};"
        : "+f"(c[0]), "+f"(c[1]), "+f"(c[2]), "+f"(c[3])
        : "r"(a[0]), "r"(a[1]), "r"(a[2]), "r"(a[3]), "r"(b0), "r"(b1));
}
__device__ __forceinline__ void ldm_x4(uint32_t addr, uint32_t* r) {
    asm volatile("ldmatrix.sync.aligned.m8n8.x4.shared.b16 {%0,%1,%2,%3}, [%4];"
        : "=r"(r[0]), "=r"(r[1]), "=r"(r[2]), "=r"(r[3]) : "r"(addr));
}
__device__ __forceinline__ uint32_t smem_u32(const void* p) {
    uint32_t a; asm("{ .reg .u64 t; cvta.to.shared.u64 t, %1; cvt.u32.u64 %0, t; }" : "=r"(a) : "l"(p));
    return a;
}

__device__ __forceinline__ int inv_perm(int s) {
    int c2 = s / 6, r = s % 6, j = r >> 1, b = r & 1;
    return (2*c2 + b)*3 + j;
}

__global__ void init_kernel() {
    int t = threadIdx.x;
    if (t < 5) g_maxPre[t]  = 0x007FFFFFu;
    if (t < 4) g_maxPost[t] = 0x007FFFFFu;
}

__device__ __forceinline__ uint4 make_bfrag(float w00, float w01, float w10, float w11) {
    uint32_t u00 = __float_as_uint(w00), u01 = __float_as_uint(w01);
    uint32_t u10 = __float_as_uint(w10), u11 = __float_as_uint(w11);
    uint4 f;
    f.x = __byte_perm(u00, u01, 0x7632);
    f.y = __byte_perm(u10, u11, 0x7632);
    f.z = bf16x2_rn(w00 - __uint_as_float(u00 & 0xFFFF0000u),
                    w01 - __uint_as_float(u01 & 0xFFFF0000u));
    f.w = bf16x2_rn(w10 - __uint_as_float(u10 & 0xFFFF0000u),
                    w11 - __uint_as_float(u11 & 0xFFFF0000u));
    return f;
}

__global__ void prep_weights(const float* __restrict__ w_perc, const float* __restrict__ b_perc,
                             const float* __restrict__ w1, const float* __restrict__ w2,
                             const float* __restrict__ w3) {
    int t = threadIdx.x;
    for (int idx = t; idx < 8*9*9; idx += 256) {
        int c2 = idx / 81, r = idx % 81, dh = r / 9, kk = r % 9, kw = kk / 3, j = kk % 3;
        int kf = dh*3 + kw;
        g_Wq[(c2*9 + dh)*12 + kw*3 + j] =
            pack2(w_perc[((2*c2)*3 + j)*27 + kf], w_perc[((2*c2+1)*3 + j)*27 + kf]);
    }
    if (t < 24) {
        int c2 = t / 3, j = t % 3;
        g_Bpp[t] = pack2(b_perc[(2*c2)*3 + j], b_perc[(2*c2+1)*3 + j]);
    }
    for (int idx = t; idx < 3*8*32; idx += 256) {
        int kt = idx >> 8, n = (idx >> 5) & 7, l = idx & 31;
        int g = l >> 2, q = l & 3, ro = n*8 + g;
        int s0 = kt*16 + 2*q;
        g_Wb1[idx] = make_bfrag(w1[ro*48 + inv_perm(s0)],   w1[ro*48 + inv_perm(s0+1)],
                                w1[ro*48 + inv_perm(s0+8)], w1[ro*48 + inv_perm(s0+9)]);
    }
    for (int idx = t; idx < 4*8*32; idx += 256) {
        int kt = idx >> 8, n = (idx >> 5) & 7, l = idx & 31;
        int g = l >> 2, q = l & 3, ro = n*8 + g;
        int s0 = kt*16 + 2*q;
        g_Wb2[idx] = make_bfrag(w2[ro*64 + s0],   w2[ro*64 + s0+1],
                                w2[ro*64 + s0+8], w2[ro*64 + s0+9]);
    }
    for (int idx = t; idx < 4*2*32; idx += 256) {
        int kt = idx >> 6, n = (idx >> 5) & 1, l = idx & 31;
        int g = l >> 2, q = l & 3, ro = n*8 + g;
        int s0 = kt*16 + 2*q;
        g_Wb3[idx] = make_bfrag(w3[ro*64 + s0],   w3[ro*64 + s0+1],
                                w3[ro*64 + s0+8], w3[ro*64 + s0+9]);
    }
}

__global__ void reduce_ch3_kernel(const float* __restrict__ p) {
    float m = -INFINITY;
    for (int i = blockIdx.x * blockDim.x + threadIdx.x; i < VOL; i += gridDim.x * blockDim.x)
        m = fmaxf(m, p[i]);
    #pragma unroll
    for (int s = 16; s > 0; s >>= 1) m = fmaxf(m, __shfl_xor_sync(0xffffffffu, m, s));
    __shared__ float sm[8];
    if ((threadIdx.x & 31) == 0) sm[threadIdx.x >> 5] = m;
    __syncthreads();
    if (threadIdx.x == 0) {
        int nw = (blockDim.x + 31) / 32;
        float mm = sm[0];
        for (int i = 1; i < nw; i++) mm = fmaxf(mm, sm[i]);
        atomicMax(&g_maxPre[0], encf(mm));
    }
}

// Layer-1 MMA pass from smem (conv activations): 32 rows x 64 outputs, 3 k16-tiles.
__device__ __forceinline__ void mma_pass1(uint32_t rowHi, uint32_t rowLo,
                                          uint32_t xr, uint32_t hi4,
                                          int lane, float C[2][8][4])
{
    #pragma unroll
    for (int m = 0; m < 2; m++)
        #pragma unroll
        for (int n = 0; n < 8; n++)
            #pragma unroll
            for (int i = 0; i < 4; i++) C[m][n][i] = 0.0f;

    #pragma unroll
    for (int k = 0; k < 3; k++) {
        uint32_t off0 = ((2u*k + hi4) ^ xr) << 4;
        uint32_t off1 = ((2u*k + hi4) ^ xr ^ 2u) << 4;   // rows +16: xr flips bit1
        uint32_t h0[4], h1[4], l0[4], l1[4];
        ldm_x4(rowHi + off0, h0);
        ldm_x4(rowHi + 16*SSTR2*2 + off1, h1);
        ldm_x4(rowLo + off0, l0);
        ldm_x4(rowLo + 16*SSTR2*2 + off1, l1);
        #pragma unroll
        for (int n = 0; n < 8; n++) {
            uint4 wf = g_Wb1[(k*8 + n)*32 + lane];
            mma_bf16(C[0][n], h0, wf.x, wf.y);
            mma_bf16(C[0][n], l0, wf.x, wf.y);
            mma_bf16(C[0][n], h0, wf.z, wf.w);
            mma_bf16(C[1][n], h1, wf.x, wf.y);
            mma_bf16(C[1][n], l1, wf.x, wf.y);
            mma_bf16(C[1][n], h1, wf.z, wf.w);
        }
    }
}

// Register-chained layer: Cin[2][8][4] --tanh+bias+split--> MMA --> Cout[2][NT][4]
template<int NT>
__device__ __forceinline__ void mma_chain(const float Cin[2][8][4], const float* sbias,
                                          const uint4* __restrict__ Wf,
                                          int lane, int q, float Cout[2][NT][4])
{
    #pragma unroll
    for (int m = 0; m < 2; m++)
        #pragma unroll
        for (int n = 0; n < NT; n++)
            #pragma unroll
            for (int i = 0; i < 4; i++) Cout[m][n][i] = 0.0f;

    #pragma unroll
    for (int kt = 0; kt < 4; kt++) {
        float b0 = sbias[16*kt + 2*q],     b1 = sbias[16*kt + 2*q + 1];
        float b2 = sbias[16*kt + 8 + 2*q], b3 = sbias[16*kt + 8 + 2*q + 1];
        uint32_t ah[2][4], al[2][4];
        #pragma unroll
        for (int m = 0; m < 2; m++) {
            cvt_frag(Cin[m][2*kt][0],   Cin[m][2*kt][1],   b0, b1, ah[m][0], al[m][0]);
            cvt_frag(Cin[m][2*kt][2],   Cin[m][2*kt][3],   b0, b1, ah[m][1], al[m][1]);
            cvt_frag(Cin[m][2*kt+1][0], Cin[m][2*kt+1][1], b2, b3, ah[m][2], al[m][2]);
            cvt_frag(Cin[m][2*kt+1][2], Cin[m][2*kt+1][3], b2, b3, ah[m][3], al[m][3]);
        }
        #pragma unroll
        for (int n = 0; n < NT; n++) {
            uint4 wf = Wf[(kt*NT + n)*32 + lane];
            mma_bf16(Cout[0][n], ah[0], wf.x, wf.y);
            mma_bf16(Cout[0][n], al[0], wf.x, wf.y);
            mma_bf16(Cout[0][n], ah[0], wf.z, wf.w);
            mma_bf16(Cout[1][n], ah[1], wf.x, wf.y);
            mma_bf16(Cout[1][n], al[1], wf.x, wf.y);
            mma_bf16(Cout[1][n], ah[1], wf.z, wf.w);
        }
    }
}

// Persistent update: 592 blocks, each strides over tiles. Block tile = 192 voxels
// (2 h-rows), 96 threads (2 voxels each), 3 warps; warp-private smem rows.
// Conv weights live in the dead 16B/row chunk slot (halves 64..71) of the planes.
__global__ __launch_bounds__(96, 4) void update_kernel(
    const float* __restrict__ xin,
    const float* __restrict__ b1, const float* __restrict__ b2, const float* __restrict__ b3,
    int step)
{
    const float* cur = (step == 0) ? xin : (const float*)g_A;

    extern __shared__ uint16_t SH[];
    uint16_t* Shi = SH;
    uint16_t* Slo = SH + PLANE_H;
    __shared__ float sb1[64], sb2[64], sb3[16];
    __shared__ u64t  sbq[24];

    const int t = threadIdx.x;
    const int lane = t & 31;
    if (t < 64) { sb1[t] = b1[t]; sb2[t] = b2[t]; }
    if (t < 16) sb3[t] = b3[t];
    if (t >= 64 && t < 88) sbq[t - 64] = g_Bpp[t - 64];
    // stash conv weights in dead chunk space: group g -> rows 5g..5g+4, halves 64..71
    for (int i = t; i < 648; i += 96) {
        int gq = i / 9, j = i % 9;
        u64t v = g_Wq[gq*12 + j];
        *(u64t*)&SH[(5*gq + (j >> 1))*SSTR2 + 64 + (j & 1)*4] = v;
    }
    __syncthreads();

    const int wid = t >> 5;
    const int g = lane >> 2, q = lane & 3;
    const uint32_t sbase = smem_u32(Shi);
    const uint32_t hi4 = lane >> 4;
    float mPost = -INFINITY;

    for (int tile = blockIdx.x; tile < NTILES; tile += NBLK) {
        const int bb = tile * 192;
        const int d  = tile / 48;
        const int h0 = (tile % 48) * 2;
        const int lv = 2*t;
        const int w0 = lv % 96;
        const int h  = h0 + lv / 96;
        const int p0 = bb + lv;

        const bool vD[3] = { d > 0, true, d < DD-1 };
        const bool vH[3] = { h > 0, true, h < DD-1 };
        const bool wl = (w0 > 0), wr = (w0 < 94);

        // ---- depthwise conv: 2 voxels/thread, weights from smem stash ----
        {
            float aA = -INFINITY, aB = -INFINITY;
            #pragma unroll 2
            for (int c2 = 0; c2 < 8; c2++) {
                u64t fA0 = sbq[c2*3+0], fA1 = sbq[c2*3+1], fA2 = sbq[c2*3+2];
                u64t fB0 = fA0, fB1 = fA1, fB2 = fA2;
                const float* baseA = cur + (2*c2)*VOL;
                const float* baseB = baseA + VOL;
                #pragma unroll
                for (int kd = 0; kd < 3; kd++)
                    #pragma unroll
                    for (int kh = 0; kh < 3; kh++) {
                        const bool v = vD[kd] && vH[kh];
                        const int nb = p0 + (kd-1)*PLN + (kh-1)*DD;
                        float2 ca = make_float2(0.0f, 0.0f), cb = make_float2(0.0f, 0.0f);
                        if (v) {
                            ca = *reinterpret_cast<const float2*>(baseA + nb);
                            cb = *reinterpret_cast<const float2*>(baseB + nb);
                        }
                        float ma = __shfl_up_sync(0xffffffffu, ca.y, 1);
                        float mb = __shfl_up_sync(0xffffffffu, cb.y, 1);
                        float pa = __shfl_down_sync(0xffffffffu, ca.x, 1);
                        float pb = __shfl_down_sync(0xffffffffu, cb.x, 1);
                        if (lane == 0 && v && wl)  { ma = baseA[nb-1]; mb = baseB[nb-1]; }
                        if (lane == 31 && v && wr) { pa = baseA[nb+2]; pb = baseB[nb+2]; }
                        if (!wl) { ma = 0.0f; mb = 0.0f; }
                        if (!wr) { pa = 0.0f; pb = 0.0f; }
                        if (c2 == 1 && v) {   // channel 3 (hi lane) alive pool
                            float mx = fmaxf(cb.x, cb.y);
                            aA = fmaxf(aA, mx); if (wl) aA = fmaxf(aA, mb);
                            aB = fmaxf(aB, mx); if (wr) aB = fmaxf(aB, pb);
                        }
                        const uint16_t* wb = SH + (5*(c2*9 + kd*3 + kh))*SSTR2 + 64;
                        ulonglong2 q0 = *(const ulonglong2*)(wb);
                        ulonglong2 q1 = *(const ulonglong2*)(wb + SSTR2);
                        ulonglong2 q2 = *(const ulonglong2*)(wb + 2*SSTR2);
                        ulonglong2 q3 = *(const ulonglong2*)(wb + 3*SSTR2);
                        u64t w8 = *(const u64t*)(wb + 4*SSTR2);
                        u64t Pm = pack2(ma, mb), Pc0 = pack2(ca.x, cb.x);
                        u64t Pc1 = pack2(ca.y, cb.y), Pp = pack2(pa, pb);
                        fA0 = ffma2(Pm,  q0.x, fA0); fA1 = ffma2(Pm,  q0.y, fA1); fA2 = ffma2(Pm,  q1.x, fA2);
                        fA0 = ffma2(Pc0, q1.y, fA0); fA1 = ffma2(Pc0, q2.x, fA1); fA2 = ffma2(Pc0, q2.y, fA2);
                        fA0 = ffma2(Pc1, q3.x, fA0); fA1 = ffma2(Pc1, q3.y, fA1); fA2 = ffma2(Pc1, w8,   fA2);
                        fB0 = ffma2(Pc0, q0.x, fB0); fB1 = ffma2(Pc0, q0.y, fB1); fB2 = ffma2(Pc0, q1.x, fB2);
                        fB0 = ffma2(Pc1, q1.y, fB0); fB1 = ffma2(Pc1, q2.x, fB1); fB2 = ffma2(Pc1, q2.y, fB2);
                        fB0 = ffma2(Pp,  q3.x, fB0); fB1 = ffma2(Pp,  q3.y, fB1); fB2 = ffma2(Pp,  w8,   fB2);
                    }
                float lo, hi;
                unpack2(fA0, lo, hi); st_pair(Shi, Slo, lv,   6*c2+0, lo, hi);
                unpack2(fA1, lo, hi); st_pair(Shi, Slo, lv,   6*c2+2, lo, hi);
                unpack2(fA2, lo, hi); st_pair(Shi, Slo, lv,   6*c2+4, lo, hi);
                unpack2(fB0, lo, hi); st_pair(Shi, Slo, lv+1, 6*c2+0, lo, hi);
                unpack2(fB1, lo, hi); st_pair(Shi, Slo, lv+1, 6*c2+2, lo, hi);
                unpack2(fB2, lo, hi); st_pair(Shi, Slo, lv+1, 6*c2+4, lo, hi);
            }
            *reinterpret_cast<float2*>(&g_alive0[p0]) = make_float2(aA, aB);
        }
        __syncwarp();

        #pragma unroll
        for (int pass = 0; pass < 2; pass++) {
            const int base_r = wid*64 + pass*32;
            const int rr = base_r + (lane & 15);
            const uint32_t xr = ((uint32_t)rr >> 3) & 7u;
            const uint32_t rowHi = sbase + rr*SSTR2*2;
            const uint32_t rowLo = rowHi + PLANE_B;

            // layer 1 (smem), layers 2+3 register-chained
            float C1[2][8][4];
            mma_pass1(rowHi, rowLo, xr, hi4, lane, C1);
            float C2[2][8][4];
            mma_chain<8>(C1, sb1, g_Wb2, lane, q, C2);
            float C3[2][2][4];
            mma_chain<2>(C2, sb2, g_Wb3, lane, q, C3);

            // epilogue: residual + store
            #pragma unroll
            for (int m = 0; m < 2; m++) {
                int rA = base_r + m*16 + g;
                int pA = bb + rA, pB = pA + 8;
                #pragma unroll
                for (int n = 0; n < 2; n++) {
                    int c0 = 8*n + 2*q, c1 = c0 + 1;
                    float v00 = C3[m][n][0] + sb3[c0] + cur[c0*VOL + pA];
                    float v01 = C3[m][n][1] + sb3[c1] + cur[c1*VOL + pA];
                    float v10 = C3[m][n][2] + sb3[c0] + cur[c0*VOL + pB];
                    float v11 = C3[m][n][3] + sb3[c1] + cur[c1*VOL + pB];
                    g_B[c0*VOL + pA] = v00;
                    g_B[c1*VOL + pA] = v01;
                    g_B[c0*VOL + pB] = v10;
                    g_B[c1*VOL + pB] = v11;
                    if (c1 == 3) mPost = fmaxf(mPost, fmaxf(v01, v11));
                }
            }
        }
        __syncwarp();
    }

    #pragma unroll
    for (int s = 16; s > 0; s >>= 1) mPost = fmaxf(mPost, __shfl_xor_sync(0xffffffffu, mPost, s));
    if (lane == 0) atomicMax(&g_maxPost[step], encf(mPost));
}

// Finalize: 4 voxels/thread via float4. Block 96 = 24 w-quads x 4 h-rows; grid (24, 96).
__global__ __launch_bounds__(96) void finalize_kernel(
    float* __restrict__ out, int step, const int* __restrict__ pInOut)
{
    float* dst = (step == 3) ? out : (float*)g_A;

    const int t = threadIdx.x;
    const int wq = t % 24, hr = t / 24;
    const int d = blockIdx.y;
    const int h = blockIdx.x * 4 + hr;
    const int w = wq * 4;
    const int pos = d*PLN + h*DD + w;

    const bool vD[3] = { d > 0, true, d < DD-1 };
    const bool vH[3] = { h > 0, true, h < DD-1 };
    const bool wl = (w > 0), wr = (w < 92);

    const float* B3 = g_B + 3*VOL;
    float4 m4 = make_float4(-INFINITY, -INFINITY, -INFINITY, -INFINITY);
    float eL = -INFINITY, eR = -INFINITY;
    #pragma unroll
    for (int kd = 0; kd < 3; kd++)
        #pragma unroll
        for (int kh = 0; kh < 3; kh++)
            if (vD[kd] && vH[kh]) {
                int nb = pos + (kd-1)*PLN + (kh-1)*DD;
                float4 r = *reinterpret_cast<const float4*>(B3 + nb);
                m4.x = fmaxf(m4.x, r.x); m4.y = fmaxf(m4.y, r.y);
                m4.z = fmaxf(m4.z, r.z); m4.w = fmaxf(m4.w, r.w);
                if (wl) eL = fmaxf(eL, B3[nb-1]);
                if (wr) eR = fmaxf(eR, B3[nb+4]);
            }
    float m1_0 = fmaxf(fmaxf(eL,   m4.x), m4.y);
    float m1_1 = fmaxf(fmaxf(m4.x, m4.y), m4.z);
    float m1_2 = fmaxf(fmaxf(m4.y, m4.z), m4.w);
    float m1_3 = fmaxf(fmaxf(m4.z, m4.w), eR);

    float th0 = 0.1f * decf(g_maxPre[step]);  if (isnan(th0)) th0 = -INFINITY;
    float th1 = 0.1f * decf(g_maxPost[step]); if (isnan(th1)) th1 = -INFINITY;

    float4 a0 = *reinterpret_cast<const float4*>(g_alive0 + pos);
    bool zero = (d == DD-1) && (h >= *pInOut);
    float lf0 = (!zero && a0.x > th0 && m1_0 > th1) ? 1.0f : 0.0f;
    float lf1 = (!zero && a0.y > th0 && m1_1 > th1) ? 1.0f : 0.0f;
    float lf2 = (!zero && a0.z > th0 && m1_2 > th1) ? 1.0f : 0.0f;
    float lf3 = (!zero && a0.w > th0 && m1_3 > th1) ? 1.0f : 0.0f;

    float v3 = -INFINITY;
    #pragma unroll
    for (int c = 0; c < NC; c++) {
        float4 v = *reinterpret_cast<const float4*>(g_B + c*VOL + pos);
        v.x *= lf0; v.y *= lf1; v.z *= lf2; v.w *= lf3;
        *reinterpret_cast<float4*>(dst + c*VOL + pos) = v;
        if (c == 3) v3 = fmaxf(fmaxf(v.x, v.y), fmaxf(v.z, v.w));
    }

    #pragma unroll
    for (int s = 16; s > 0; s >>= 1) v3 = fmaxf(v3, __shfl_xor_sync(0xffffffffu, v3, s));
    if ((t & 31) == 0) atomicMax(&g_maxPre[step + 1], encf(v3));
}

extern "C" void kernel_launch(void* const* d_in, const int* in_sizes, int n_in,
                              void* d_out, int out_size) {
    (void)in_sizes; (void)n_in; (void)out_size;
    const float* x      = (const float*)d_in[0];
    const float* w_perc = (const float*)d_in[1];
    const float* b_perc = (const float*)d_in[2];
    const float* w1     = (const float*)d_in[3];
    const float* b1     = (const float*)d_in[4];
    const float* w2     = (const float*)d_in[5];
    const float* b2     = (const float*)d_in[6];
    const float* w3     = (const float*)d_in[7];
    const float* b3     = (const float*)d_in[8];
    const int*   pInOut = (const int*)d_in[12];
    float* out = (float*)d_out;

    static bool attr_set = false;
    if (!attr_set) {
        cudaFuncSetAttribute(update_kernel, cudaFuncAttributeMaxDynamicSharedMemorySize, SMEM_BYTES);
        attr_set = true;
    }

    init_kernel<<<1, 32>>>();
    prep_weights<<<1, 256>>>(w_perc, b_perc, w1, w2, w3);
    reduce_ch3_kernel<<<432, 256>>>(x + 3*VOL);

    dim3 fgrd(24, DD);
    for (int s = 0; s < 4; s++) {
        update_kernel<<<NBLK, 96, SMEM_BYTES>>>(x, b1, b2, b3, s);
        finalize_kernel<<<fgrd, 96>>>(out, s, pInOut);
    }
}